// round 1
// baseline (speedup 1.0000x reference)
#include <cuda_runtime.h>
#include <math.h>

#define BB   128
#define DD   20000
#define DM1  19999
#define HID  128
#define LOG2PI 1.8378770664093453

// ---------------- device scratch (no allocations allowed) ----------------
__device__ double d_P[(size_t)BB * (DD + 1)];      // fp64 prefix sums of log(x+1)
__device__ float  d_hx[(size_t)BB * DM1];          // ilr-transformed x
__device__ float  d_dlt[(size_t)BB * (DD + 1)];    // difference array for logits
__device__ float  d_z[BB * HID];
__device__ float  d_g[BB * HID];
__device__ float  d_WtW[HID * HID];
__device__ float  d_u[BB * HID];
__device__ int    d_lo[DM1], d_mid[DM1], d_hi[DM1];
__device__ float  d_av[DM1], d_bv[DM1];
__device__ double d_sumx[BB], d_sumlg[BB], d_mult[BB];
__device__ float  d_eta2[BB];
__device__ float  d_zg[BB], d_zWz[BB], d_z2[BB];

// ---------------- meta: recover (lo,mid,hi,a,b) per Psi row ----------------
__device__ __forceinline__ int lower_bound_i(const int* a, int n, int key) {
    int lo = 0, hi = n;
    while (lo < hi) { int m = (lo + hi) >> 1; if (a[m] < key) lo = m + 1; else hi = m; }
    return lo;
}

__global__ void k_meta(const int* __restrict__ rows, const int* __restrict__ cols,
                       const float* __restrict__ vals, int nnz) {
    int r = blockIdx.x * blockDim.x + threadIdx.x;
    if (r >= DM1) return;
    int s = lower_bound_i(rows, nnz, r);
    int e = lower_bound_i(rows, nnz, r + 1);
    d_lo[r] = cols[s];
    d_hi[r] = cols[e - 1] + 1;
    d_av[r] = vals[s];
    d_bv[r] = vals[e - 1];
    // first negative value in [s,e) -> mid
    int a = s, b = e;
    while (a < b) { int m = (a + b) >> 1; if (vals[m] < 0.f) b = m; else a = m + 1; }
    d_mid[r] = cols[a];
}

// ---------------- per-row prefix scan of log(x+1) in fp64 ----------------
__global__ void k_scan_lx(const float* __restrict__ x) {
    int b = blockIdx.x, t = threadIdx.x;
    const float* xb = x + (size_t)b * DD;
    double* Pb = d_P + (size_t)b * (DD + 1);
    __shared__ double sh[256];
    double carry = 0.0, sx = 0.0, sg = 0.0;
    if (t == 0) Pb[0] = 0.0;
    for (int base = 0; base < DD; base += 2048) {
        double loc[8]; double run = 0.0;
        int i0 = base + t * 8;
        #pragma unroll
        for (int v = 0; v < 8; v++) {
            int i = i0 + v;
            if (i < DD) {
                float xv = xb[i];
                sx += (double)xv;
                sg += (double)lgammaf(xv + 1.f);
                run += (double)logf(xv + 1.f);
            }
            loc[v] = run;
        }
        sh[t] = run;
        __syncthreads();
        for (int off = 1; off < 256; off <<= 1) {
            double add = (t >= off) ? sh[t - off] : 0.0;
            __syncthreads();
            sh[t] += add;
            __syncthreads();
        }
        double excl = (t > 0) ? sh[t - 1] : 0.0;
        double tot = sh[255];
        #pragma unroll
        for (int v = 0; v < 8; v++) {
            int i = i0 + v;
            if (i < DD) Pb[i + 1] = carry + excl + loc[v];
        }
        carry += tot;
        __syncthreads();
    }
    sh[t] = sx; __syncthreads();
    for (int off = 128; off; off >>= 1) { if (t < off) sh[t] += sh[t + off]; __syncthreads(); }
    if (t == 0) d_sumx[b] = sh[0];
    __syncthreads();
    sh[t] = sg; __syncthreads();
    for (int off = 128; off; off >>= 1) { if (t < off) sh[t] += sh[t + off]; __syncthreads(); }
    if (t == 0) d_sumlg[b] = sh[0];
}

// ---------------- hx from prefix sums ----------------
__global__ void k_hx() {
    int r = blockIdx.x * blockDim.x + threadIdx.x;
    int b = blockIdx.y;
    if (r >= DM1) return;
    const double* Pb = d_P + (size_t)b * (DD + 1);
    double pl = Pb[d_lo[r]], pm = Pb[d_mid[r]], ph = Pb[d_hi[r]];
    d_hx[(size_t)b * DM1 + r] = d_av[r] * (float)(pm - pl) + d_bv[r] * (float)(ph - pm);
}

// ---------------- logits scatter (difference array) + eta^2 ----------------
__global__ void k_scatter(const float* __restrict__ eta) {
    int r = blockIdx.x * blockDim.x + threadIdx.x;
    int b = blockIdx.y;
    float e = 0.f;
    if (r < DM1) {
        e = eta[(size_t)b * DM1 + r];
        float a = d_av[r], bb = d_bv[r];
        float* db = d_dlt + (size_t)b * (DD + 1);
        atomicAdd(db + d_lo[r], a * e);
        atomicAdd(db + d_mid[r], (bb - a) * e);
        atomicAdd(db + d_hi[r], -bb * e);
    }
    __shared__ float sred[256];
    sred[threadIdx.x] = e * e;
    __syncthreads();
    for (int off = 128; off; off >>= 1) {
        if (threadIdx.x < off) sred[threadIdx.x] += sred[threadIdx.x + off];
        __syncthreads();
    }
    if (threadIdx.x == 0) atomicAdd(&d_eta2[b], sred[0]);
}

// ---------------- logits scan + multinomial logprob ----------------
__global__ void k_mult(const float* __restrict__ x) {
    int b = blockIdx.x, t = threadIdx.x;
    const float* xb = x + (size_t)b * DD;
    const float* db = d_dlt + (size_t)b * (DD + 1);
    __shared__ double sh[256];
    double carry = 0.0, sexp = 0.0, sxl = 0.0;
    for (int base = 0; base < DD; base += 2048) {
        float loc[8], xv[8]; float run = 0.f;
        int i0 = base + t * 8;
        #pragma unroll
        for (int v = 0; v < 8; v++) {
            int i = i0 + v;
            float dv = (i < DD) ? db[i] : 0.f;
            xv[v] = (i < DD) ? xb[i] : 0.f;
            run += dv;
            loc[v] = run;
        }
        sh[t] = (double)run;
        __syncthreads();
        for (int off = 1; off < 256; off <<= 1) {
            double add = (t >= off) ? sh[t - off] : 0.0;
            __syncthreads();
            sh[t] += add;
            __syncthreads();
        }
        double excl = (t > 0) ? sh[t - 1] : 0.0;
        double tot = sh[255];
        #pragma unroll
        for (int v = 0; v < 8; v++) {
            int i = i0 + v;
            if (i < DD) {
                double logit = carry + excl + (double)loc[v];
                sexp += exp(logit);
                sxl += (double)xv[v] * logit;
            }
        }
        carry += tot;
        __syncthreads();
    }
    sh[t] = sexp; __syncthreads();
    for (int off = 128; off; off >>= 1) { if (t < off) sh[t] += sh[t + off]; __syncthreads(); }
    double tsexp = sh[0];
    __syncthreads();
    sh[t] = sxl; __syncthreads();
    for (int off = 128; off; off >>= 1) { if (t < off) sh[t] += sh[t + off]; __syncthreads(); }
    if (t == 0) {
        double sx = d_sumx[b];
        d_mult[b] = lgamma(sx + 1.0) - d_sumlg[b] + sh[0] - sx * log(tsexp);
    }
}

// ---------------- GEMM: z = hx @ enc_w^T (split-K, atomic reduce) ----------------
#define TJ 32
#define JC 128
__global__ __launch_bounds__(256) void k_gemm_z(const float* __restrict__ Bm) {
    __shared__ float As[TJ][129];
    __shared__ float Bs[TJ][129];
    int j0 = blockIdx.x * JC;
    int jend = min(j0 + JC, DM1);
    int t = threadIdx.x, tx = t & 15, ty = t >> 4;
    float acc[8][8];
    #pragma unroll
    for (int i = 0; i < 8; i++)
        #pragma unroll
        for (int j = 0; j < 8; j++) acc[i][j] = 0.f;

    for (int jt = j0; jt < jend; jt += TJ) {
        #pragma unroll
        for (int l = 0; l < 16; l++) {
            int idx = t + 256 * l;
            int jj = idx & 31, row = idx >> 5;
            int j = jt + jj;
            float av = 0.f, bv = 0.f;
            if (j < jend) {
                av = d_hx[(size_t)row * DM1 + j];
                bv = Bm[(size_t)row * DM1 + j];
            }
            As[jj][row] = av;
            Bs[jj][row] = bv;
        }
        __syncthreads();
        #pragma unroll
        for (int jj = 0; jj < TJ; jj++) {
            float af[8], bf[8];
            #pragma unroll
            for (int i = 0; i < 8; i++) { af[i] = As[jj][ty + 16 * i]; bf[i] = Bs[jj][tx + 16 * i]; }
            #pragma unroll
            for (int i = 0; i < 8; i++)
                #pragma unroll
                for (int j2 = 0; j2 < 8; j2++) acc[i][j2] = fmaf(af[i], bf[j2], acc[i][j2]);
        }
        __syncthreads();
    }
    #pragma unroll
    for (int i = 0; i < 8; i++)
        #pragma unroll
        for (int j2 = 0; j2 < 8; j2++)
            atomicAdd(&d_z[(ty + 16 * i) * HID + tx + 16 * j2], acc[i][j2]);
}

// ---------------- fused GEMM: g = eta @ dec_w  and  WtW = dec_w^T dec_w ----------------
__global__ __launch_bounds__(256) void k_gemm_gw(const float* __restrict__ eta,
                                                 const float* __restrict__ dw) {
    __shared__ float Es[TJ][129];
    __shared__ float Ds[TJ][129];
    int j0 = blockIdx.x * JC;
    int jend = min(j0 + JC, DM1);
    int t = threadIdx.x, tx = t & 15, ty = t >> 4;
    float accg[8][8], accw[8][8];
    #pragma unroll
    for (int i = 0; i < 8; i++)
        #pragma unroll
        for (int j = 0; j < 8; j++) { accg[i][j] = 0.f; accw[i][j] = 0.f; }

    for (int jt = j0; jt < jend; jt += TJ) {
        #pragma unroll
        for (int l = 0; l < 16; l++) {
            int idx = t + 256 * l;
            int jj = idx & 31, row = idx >> 5;
            int j = jt + jj;
            Es[jj][row] = (j < jend) ? eta[(size_t)row * DM1 + j] : 0.f;
        }
        #pragma unroll
        for (int l = 0; l < 16; l++) {
            int idx = t + 256 * l;
            int k = idx & 127, jj = idx >> 7;
            int j = jt + jj;
            Ds[jj][k] = (j < jend) ? dw[(size_t)j * HID + k] : 0.f;
        }
        __syncthreads();
        #pragma unroll
        for (int jj = 0; jj < TJ; jj++) {
            float ef[8], dk[8], dy[8];
            #pragma unroll
            for (int i = 0; i < 8; i++) {
                ef[i] = Es[jj][ty + 16 * i];
                dk[i] = Ds[jj][tx + 16 * i];
                dy[i] = Ds[jj][ty + 16 * i];
            }
            #pragma unroll
            for (int i = 0; i < 8; i++)
                #pragma unroll
                for (int j2 = 0; j2 < 8; j2++) {
                    accg[i][j2] = fmaf(ef[i], dk[j2], accg[i][j2]);
                    accw[i][j2] = fmaf(dy[i], dk[j2], accw[i][j2]);
                }
        }
        __syncthreads();
    }
    #pragma unroll
    for (int i = 0; i < 8; i++)
        #pragma unroll
        for (int j2 = 0; j2 < 8; j2++) {
            atomicAdd(&d_g[(ty + 16 * i) * HID + tx + 16 * j2], accg[i][j2]);
            atomicAdd(&d_WtW[(ty + 16 * i) * HID + tx + 16 * j2], accw[i][j2]);
        }
}

// ---------------- u = (g - z@WtW)*sD, per-b quadratic pieces ----------------
__global__ void k_uquad(const float* __restrict__ vlv) {
    int b = blockIdx.x, k = threadIdx.x;
    __shared__ float zs[128];
    __shared__ float rd[128];
    zs[k] = d_z[b * HID + k];
    __syncthreads();
    float w = 0.f;
    #pragma unroll 8
    for (int k2 = 0; k2 < 128; k2++) w = fmaf(zs[k2], d_WtW[k2 * HID + k], w);
    float g = d_g[b * HID + k];
    float sd = expf(0.5f * vlv[k]);
    d_u[b * HID + k] = (g - w) * sd;
    float z = zs[k];

    rd[k] = z * g; __syncthreads();
    for (int off = 64; off; off >>= 1) { if (k < off) rd[k] += rd[k + off]; __syncthreads(); }
    if (k == 0) d_zg[b] = rd[0];
    __syncthreads();
    rd[k] = z * w; __syncthreads();
    for (int off = 64; off; off >>= 1) { if (k < off) rd[k] += rd[k + off]; __syncthreads(); }
    if (k == 0) d_zWz[b] = rd[0];
    __syncthreads();
    rd[k] = z * z; __syncthreads();
    for (int off = 64; off; off >>= 1) { if (k < off) rd[k] += rd[k + off]; __syncthreads(); }
    if (k == 0) d_z2[b] = rd[0];
}

// ---------------- final: Cholesky, forward solve, loss assembly ----------------
__global__ void k_final(const float* __restrict__ vlv,
                        const float* __restrict__ lss_ptr,
                        float* __restrict__ out) {
    extern __shared__ float smf[];
    float* Mm = smf;                 // 128 x 129
    float* R  = smf + 128 * 129;     // 128 x 129 (R[i][b])
    __shared__ float sD[128], quadU[128], yrow[128];
    __shared__ float s_diag;
    __shared__ double s_ld;
    __shared__ double red[512];
    int t = threadIdx.x;
    float lss = *lss_ptr;
    float var = expf(lss);
    if (t < 128) { sD[t] = expf(0.5f * vlv[t]); quadU[t] = 0.f; }
    if (t == 0) s_ld = 0.0;
    __syncthreads();
    for (int idx = t; idx < 128 * 128; idx += 512) {
        int i = idx >> 7, j = idx & 127;
        float m = sD[i] * d_WtW[idx] * sD[j] / var;
        if (i == j) m += 1.f;
        Mm[i * 129 + j] = m;
        R[i * 129 + j] = d_u[j * HID + i];   // R[i][b] = u[b][i]
    }
    __syncthreads();
    // Cholesky (lower), full-square trailing update keeps symmetry
    for (int k = 0; k < 128; k++) {
        if (t == 0) {
            float dv = sqrtf(Mm[k * 129 + k]);
            s_diag = dv;
            s_ld += 2.0 * log((double)dv);
        }
        __syncthreads();
        float inv = 1.f / s_diag;
        for (int i = k + 1 + t; i < 128; i += 512) Mm[i * 129 + k] *= inv;
        if (t == 0) Mm[k * 129 + k] = s_diag;
        __syncthreads();
        int n = 127 - k;
        for (int q = t; q < n * n; q += 512) {
            int i = k + 1 + q / n;
            int j = k + 1 + q % n;
            Mm[i * 129 + j] -= Mm[i * 129 + k] * Mm[j * 129 + k];
        }
        __syncthreads();
    }
    // forward solve L y = u (all 128 RHS), accumulate ||y||^2 per b
    for (int j = 0; j < 128; j++) {
        if (t < 128) {
            float y = R[j * 129 + t] / Mm[j * 129 + j];
            yrow[t] = y;
            quadU[t] += y * y;
        }
        __syncthreads();
        int n = 127 - j;
        for (int q = t; q < n * 128; q += 512) {
            int i = j + 1 + (q >> 7);
            int b = q & 127;
            R[i * 129 + b] -= Mm[i * 129 + j] * yrow[b];
        }
        __syncthreads();
    }
    // assemble loss
    double acc = 0.0;
    if (t < 128) {
        int b = t;
        float quad = (d_eta2[b] - 2.f * d_zg[b] + d_zWz[b]) / var - quadU[b] / (var * var);
        double logdet = (double)DM1 * (double)lss + s_ld;
        double ll = -0.5 * ((double)DM1 * LOG2PI + logdet + (double)quad);
        acc = ll + d_mult[b] - 0.5 * (double)d_z2[b] / 128.0;
    }
    red[t] = acc;
    __syncthreads();
    for (int off = 256; off; off >>= 1) { if (t < off) red[t] += red[t + off]; __syncthreads(); }
    if (t == 0) {
        double total = red[0] / 128.0 - 0.5 * LOG2PI;  // + prior constant
        out[0] = (float)(-total);
    }
}

// ---------------- launcher ----------------
extern "C" void kernel_launch(void* const* d_in, const int* in_sizes, int n_in,
                              void* d_out, int out_size) {
    const float* x     = (const float*)d_in[0];
    const int*   rows  = (const int*)  d_in[1];
    const int*   cols  = (const int*)  d_in[2];
    const float* vals  = (const float*)d_in[3];
    const float* enc_w = (const float*)d_in[4];
    const float* dec_w = (const float*)d_in[5];
    const float* vlv   = (const float*)d_in[6];
    const float* lss   = (const float*)d_in[7];
    const float* eta   = (const float*)d_in[8];
    int nnz = in_sizes[1];
    float* out = (float*)d_out;

    void *p_dlt, *p_z, *p_g, *p_w, *p_e2;
    cudaGetSymbolAddress(&p_dlt, d_dlt);
    cudaGetSymbolAddress(&p_z,   d_z);
    cudaGetSymbolAddress(&p_g,   d_g);
    cudaGetSymbolAddress(&p_w,   d_WtW);
    cudaGetSymbolAddress(&p_e2,  d_eta2);
    cudaMemsetAsync(p_dlt, 0, (size_t)BB * (DD + 1) * sizeof(float));
    cudaMemsetAsync(p_z,   0, BB * HID * sizeof(float));
    cudaMemsetAsync(p_g,   0, BB * HID * sizeof(float));
    cudaMemsetAsync(p_w,   0, HID * HID * sizeof(float));
    cudaMemsetAsync(p_e2,  0, BB * sizeof(float));

    k_meta<<<(DM1 + 255) / 256, 256>>>(rows, cols, vals, nnz);
    k_scan_lx<<<BB, 256>>>(x);

    dim3 grid_rb((DM1 + 255) / 256, BB);
    k_hx<<<grid_rb, 256>>>();
    k_scatter<<<grid_rb, 256>>>(eta);
    k_mult<<<BB, 256>>>(x);

    int nblk = (DM1 + JC - 1) / JC;
    k_gemm_z<<<nblk, 256>>>(enc_w);
    k_gemm_gw<<<nblk, 256>>>(eta, dec_w);
    k_uquad<<<BB, 128>>>(vlv);

    cudaFuncSetAttribute(k_final, cudaFuncAttributeMaxDynamicSharedMemorySize,
                         2 * 128 * 129 * (int)sizeof(float));
    k_final<<<1, 512, 2 * 128 * 129 * sizeof(float)>>>(vlv, lss, out);
}

// round 2
// speedup vs baseline: 1.5850x; 1.5850x over previous
#include <cuda_runtime.h>
#include <math.h>

#define BB   128
#define DD   20000
#define DM1  19999
#define HID  128
#define LOG2PI 1.8378770664093453

// ---------------- device scratch (no allocations allowed) ----------------
__device__ float  d_Pf[(size_t)BB * (DD + 1)];     // fp32 prefix sums of log(x+1)
__device__ float  d_dlt[(size_t)BB * (DD + 1)];    // difference array for logits
__device__ float  d_z[BB * HID];
__device__ float  d_g[BB * HID];
__device__ float  d_WtW[HID * HID];
__device__ float  d_u[BB * HID];
__device__ int    d_lo[DM1], d_mid[DM1], d_hi[DM1];
__device__ float  d_av[DM1], d_bv[DM1];
__device__ double d_sumx[BB], d_sumlg[BB], d_mult[BB];
__device__ float  d_eta2[BB];
__device__ float  d_zg[BB], d_zWz[BB], d_z2[BB];
__device__ double d_lxtab[32];   // log(i+1)
__device__ double d_lgtab[32];   // lgamma(i+1)

// ---------------- tables ----------------
__global__ void k_tables() {
    int i = threadIdx.x;
    if (i < 32) {
        d_lxtab[i] = log((double)i + 1.0);
        d_lgtab[i] = lgamma((double)i + 1.0);
    }
}

// ---------------- meta: recover (lo,mid,hi,a,b) per Psi row ----------------
__device__ __forceinline__ int lower_bound_i(const int* a, int n, int key) {
    int lo = 0, hi = n;
    while (lo < hi) { int m = (lo + hi) >> 1; if (a[m] < key) lo = m + 1; else hi = m; }
    return lo;
}

__global__ void k_meta(const int* __restrict__ rows, const int* __restrict__ cols,
                       const float* __restrict__ vals, int nnz) {
    int r = blockIdx.x * blockDim.x + threadIdx.x;
    if (r >= DM1) return;
    int s = lower_bound_i(rows, nnz, r);
    int e = lower_bound_i(rows, nnz, r + 1);
    d_lo[r] = cols[s];
    d_hi[r] = cols[e - 1] + 1;
    d_av[r] = vals[s];
    d_bv[r] = vals[e - 1];
    int a = s, b = e;
    while (a < b) { int m = (a + b) >> 1; if (vals[m] < 0.f) b = m; else a = m + 1; }
    d_mid[r] = cols[a];
}

// ---------------- per-row prefix scan of log(x+1), fp64 internal, fp32 out ----------------
__global__ __launch_bounds__(512) void k_scan_lx(const float* __restrict__ x) {
    int b = blockIdx.x, t = threadIdx.x, lane = t & 31, wid = t >> 5;
    const float* xb = x + (size_t)b * DD;
    float* Pb = d_Pf + (size_t)b * (DD + 1);
    __shared__ double wtot[16], woff[16];
    __shared__ double s_lx[32];
    __shared__ float  s_lg[32];
    __shared__ float  redf[16];
    if (t < 32) { s_lx[t] = d_lxtab[t]; s_lg[t] = (float)d_lgtab[t]; }
    __syncthreads();

    double carry = 0.0;
    float sx = 0.f, slg = 0.f;
    if (t == 0) Pb[0] = 0.f;

    for (int base = 0; base < DD; base += 4096) {
        double loc[8]; double run = 0.0;
        int i0 = base + t * 8;
        #pragma unroll
        for (int v = 0; v < 8; v++) {
            int i = i0 + v;
            if (i < DD) {
                float xv = xb[i];
                int xi = (int)xv;
                double lv; float lg;
                if (xi >= 0 && xi < 32 && (float)xi == xv) { lv = s_lx[xi]; lg = s_lg[xi]; }
                else { lv = (double)logf(xv + 1.f); lg = lgammaf(xv + 1.f); }
                sx += xv; slg += lg; run += lv;
            }
            loc[v] = run;
        }
        // warp inclusive scan of run
        double v = run;
        #pragma unroll
        for (int off = 1; off < 32; off <<= 1) {
            double nv = __shfl_up_sync(0xffffffffu, v, off);
            if (lane >= off) v += nv;
        }
        if (lane == 31) wtot[wid] = v;
        __syncthreads();
        if (wid == 0) {
            double w = (lane < 16) ? wtot[lane] : 0.0;
            #pragma unroll
            for (int off = 1; off < 16; off <<= 1) {
                double nv = __shfl_up_sync(0xffffffffu, w, off);
                if (lane >= off) w += nv;
            }
            if (lane < 16) woff[lane] = w;
        }
        __syncthreads();
        double basd = carry + (wid > 0 ? woff[wid - 1] : 0.0) + (v - run);
        #pragma unroll
        for (int u = 0; u < 8; u++) {
            int i = i0 + u;
            if (i < DD) Pb[i + 1] = (float)(basd + loc[u]);
        }
        carry += woff[15];
        __syncthreads();
    }
    // reduce sx, slg
    #pragma unroll
    for (int off = 16; off; off >>= 1) sx += __shfl_down_sync(0xffffffffu, sx, off);
    if (lane == 0) redf[wid] = sx;
    __syncthreads();
    if (t == 0) { double s = 0.0; for (int i = 0; i < 16; i++) s += (double)redf[i]; d_sumx[b] = s; }
    __syncthreads();
    #pragma unroll
    for (int off = 16; off; off >>= 1) slg += __shfl_down_sync(0xffffffffu, slg, off);
    if (lane == 0) redf[wid] = slg;
    __syncthreads();
    if (t == 0) { double s = 0.0; for (int i = 0; i < 16; i++) s += (double)redf[i]; d_sumlg[b] = s; }
}

// ---------------- logits scan + multinomial logprob (all fp32 path) ----------------
__global__ __launch_bounds__(512) void k_mult(const float* __restrict__ x) {
    int b = blockIdx.x, t = threadIdx.x, lane = t & 31, wid = t >> 5;
    const float* xb = x + (size_t)b * DD;
    const float* db = d_dlt + (size_t)b * (DD + 1);
    __shared__ float wtot[16], woff[16];
    __shared__ float redf[16];
    float carry = 0.f, sexp = 0.f, sxl = 0.f;

    for (int base = 0; base < DD; base += 4096) {
        float loc[8], xv[8]; float run = 0.f;
        int i0 = base + t * 8;
        #pragma unroll
        for (int v = 0; v < 8; v++) {
            int i = i0 + v;
            float dv = (i < DD) ? db[i] : 0.f;
            xv[v] = (i < DD) ? xb[i] : 0.f;
            run += dv;
            loc[v] = run;
        }
        float v = run;
        #pragma unroll
        for (int off = 1; off < 32; off <<= 1) {
            float nv = __shfl_up_sync(0xffffffffu, v, off);
            if (lane >= off) v += nv;
        }
        if (lane == 31) wtot[wid] = v;
        __syncthreads();
        if (wid == 0) {
            float w = (lane < 16) ? wtot[lane] : 0.f;
            #pragma unroll
            for (int off = 1; off < 16; off <<= 1) {
                float nv = __shfl_up_sync(0xffffffffu, w, off);
                if (lane >= off) w += nv;
            }
            if (lane < 16) woff[lane] = w;
        }
        __syncthreads();
        float basf = carry + (wid > 0 ? woff[wid - 1] : 0.f) + (v - run);
        #pragma unroll
        for (int u = 0; u < 8; u++) {
            int i = i0 + u;
            if (i < DD) {
                float logit = basf + loc[u];
                sexp += expf(logit);
                sxl = fmaf(xv[u], logit, sxl);
            }
        }
        carry += woff[15];
        __syncthreads();
    }
    #pragma unroll
    for (int off = 16; off; off >>= 1) sexp += __shfl_down_sync(0xffffffffu, sexp, off);
    if (lane == 0) redf[wid] = sexp;
    __syncthreads();
    double tsexp = 0.0;
    if (t == 0) { for (int i = 0; i < 16; i++) tsexp += (double)redf[i]; }
    __syncthreads();
    #pragma unroll
    for (int off = 16; off; off >>= 1) sxl += __shfl_down_sync(0xffffffffu, sxl, off);
    if (lane == 0) redf[wid] = sxl;
    __syncthreads();
    if (t == 0) {
        double s = 0.0; for (int i = 0; i < 16; i++) s += (double)redf[i];
        double sx = d_sumx[b];
        d_mult[b] = lgamma(sx + 1.0) - d_sumlg[b] + s - sx * log(tsexp);
    }
}

// ---------------- GEMM: z = hx @ enc_w^T, hx computed on the fly ----------------
#define TJ 32
#define JC 128
__global__ __launch_bounds__(256) void k_gemm_z(const float* __restrict__ Bm) {
    __shared__ float As[TJ][129];
    __shared__ float Bs[TJ][129];
    __shared__ int   slo[JC], smi[JC], shi[JC];
    __shared__ float sa[JC], sb[JC];
    int j0 = blockIdx.x * JC;
    int jend = min(j0 + JC, DM1);
    int t = threadIdx.x, tx = t & 15, ty = t >> 4;
    if (t < JC) {
        int j = j0 + t;
        if (j < jend) {
            slo[t] = d_lo[j]; smi[t] = d_mid[j]; shi[t] = d_hi[j];
            sa[t] = d_av[j];  sb[t] = d_bv[j];
        }
    }
    __syncthreads();
    float acc[8][8];
    #pragma unroll
    for (int i = 0; i < 8; i++)
        #pragma unroll
        for (int j = 0; j < 8; j++) acc[i][j] = 0.f;

    for (int jt = j0; jt < jend; jt += TJ) {
        #pragma unroll
        for (int l = 0; l < 16; l++) {
            int idx = t + 256 * l;
            int jj = idx & 31, row = idx >> 5;
            int j = jt + jj;
            float av = 0.f, bv = 0.f;
            if (j < jend) {
                int jl = j - j0;
                const float* Pb = d_Pf + (size_t)row * (DD + 1);
                float pl = Pb[slo[jl]], pm = Pb[smi[jl]], ph = Pb[shi[jl]];
                av = sa[jl] * (pm - pl) + sb[jl] * (ph - pm);
                bv = Bm[(size_t)row * DM1 + j];
            }
            As[jj][row] = av;
            Bs[jj][row] = bv;
        }
        __syncthreads();
        #pragma unroll
        for (int jj = 0; jj < TJ; jj++) {
            float af[8], bf[8];
            #pragma unroll
            for (int i = 0; i < 8; i++) { af[i] = As[jj][ty + 16 * i]; bf[i] = Bs[jj][tx + 16 * i]; }
            #pragma unroll
            for (int i = 0; i < 8; i++)
                #pragma unroll
                for (int j2 = 0; j2 < 8; j2++) acc[i][j2] = fmaf(af[i], bf[j2], acc[i][j2]);
        }
        __syncthreads();
    }
    #pragma unroll
    for (int i = 0; i < 8; i++)
        #pragma unroll
        for (int j2 = 0; j2 < 8; j2++)
            atomicAdd(&d_z[(ty + 16 * i) * HID + tx + 16 * j2], acc[i][j2]);
}

// ---- fused GEMM: g = eta @ dec_w, WtW = dec_w^T dec_w, + logits scatter + eta^2 ----
__global__ __launch_bounds__(256) void k_gemm_gw(const float* __restrict__ eta,
                                                 const float* __restrict__ dw) {
    __shared__ float Es[TJ][129];
    __shared__ float Ds[TJ][129];
    __shared__ int   slo[JC], smi[JC], shi[JC];
    __shared__ float sa[JC], sb[JC];
    int j0 = blockIdx.x * JC;
    int jend = min(j0 + JC, DM1);
    int t = threadIdx.x, tx = t & 15, ty = t >> 4;
    if (t < JC) {
        int j = j0 + t;
        if (j < jend) {
            slo[t] = d_lo[j]; smi[t] = d_mid[j]; shi[t] = d_hi[j];
            sa[t] = d_av[j];  sb[t] = d_bv[j];
        }
    }
    __syncthreads();
    float accg[8][8], accw[8][8];
    float e2[16];
    #pragma unroll
    for (int i = 0; i < 8; i++)
        #pragma unroll
        for (int j = 0; j < 8; j++) { accg[i][j] = 0.f; accw[i][j] = 0.f; }
    #pragma unroll
    for (int l = 0; l < 16; l++) e2[l] = 0.f;

    for (int jt = j0; jt < jend; jt += TJ) {
        #pragma unroll
        for (int l = 0; l < 16; l++) {
            int idx = t + 256 * l;
            int jj = idx & 31, row = idx >> 5;
            int j = jt + jj;
            float e = 0.f;
            if (j < jend) {
                int jl = j - j0;
                e = eta[(size_t)row * DM1 + j];
                float a = sa[jl], bb = sb[jl];
                float* dbp = d_dlt + (size_t)row * (DD + 1);
                atomicAdd(dbp + slo[jl], a * e);
                atomicAdd(dbp + smi[jl], (bb - a) * e);
                atomicAdd(dbp + shi[jl], -bb * e);
                e2[l] = fmaf(e, e, e2[l]);
            }
            Es[jj][row] = e;
        }
        #pragma unroll
        for (int l = 0; l < 16; l++) {
            int idx = t + 256 * l;
            int k = idx & 127, jj = idx >> 7;
            int j = jt + jj;
            Ds[jj][k] = (j < jend) ? dw[(size_t)j * HID + k] : 0.f;
        }
        __syncthreads();
        #pragma unroll
        for (int jj = 0; jj < TJ; jj++) {
            float ef[8], dk[8], dy[8];
            #pragma unroll
            for (int i = 0; i < 8; i++) {
                ef[i] = Es[jj][ty + 16 * i];
                dk[i] = Ds[jj][tx + 16 * i];
                dy[i] = Ds[jj][ty + 16 * i];
            }
            #pragma unroll
            for (int i = 0; i < 8; i++)
                #pragma unroll
                for (int j2 = 0; j2 < 8; j2++) {
                    accg[i][j2] = fmaf(ef[i], dk[j2], accg[i][j2]);
                    accw[i][j2] = fmaf(dy[i], dk[j2], accw[i][j2]);
                }
        }
        __syncthreads();
    }
    #pragma unroll
    for (int i = 0; i < 8; i++)
        #pragma unroll
        for (int j2 = 0; j2 < 8; j2++) {
            atomicAdd(&d_g[(ty + 16 * i) * HID + tx + 16 * j2], accg[i][j2]);
            atomicAdd(&d_WtW[(ty + 16 * i) * HID + tx + 16 * j2], accw[i][j2]);
        }
    // eta^2: per (warp,l) the batch row is uniform: row = (t>>5) + 8*l
    #pragma unroll
    for (int l = 0; l < 16; l++) {
        float v = e2[l];
        #pragma unroll
        for (int off = 16; off; off >>= 1) v += __shfl_down_sync(0xffffffffu, v, off);
        if ((t & 31) == 0) atomicAdd(&d_eta2[(t >> 5) + 8 * l], v);
    }
}

// ---------------- u = (g - z@WtW)*sD, per-b quadratic pieces ----------------
__global__ void k_uquad(const float* __restrict__ vlv) {
    int b = blockIdx.x, k = threadIdx.x;
    __shared__ float zs[128];
    __shared__ float rd[128];
    zs[k] = d_z[b * HID + k];
    __syncthreads();
    float w = 0.f;
    #pragma unroll 8
    for (int k2 = 0; k2 < 128; k2++) w = fmaf(zs[k2], d_WtW[k2 * HID + k], w);
    float g = d_g[b * HID + k];
    float sd = expf(0.5f * vlv[k]);
    d_u[b * HID + k] = (g - w) * sd;
    float z = zs[k];

    rd[k] = z * g; __syncthreads();
    for (int off = 64; off; off >>= 1) { if (k < off) rd[k] += rd[k + off]; __syncthreads(); }
    if (k == 0) d_zg[b] = rd[0];
    __syncthreads();
    rd[k] = z * w; __syncthreads();
    for (int off = 64; off; off >>= 1) { if (k < off) rd[k] += rd[k + off]; __syncthreads(); }
    if (k == 0) d_zWz[b] = rd[0];
    __syncthreads();
    rd[k] = z * z; __syncthreads();
    for (int off = 64; off; off >>= 1) { if (k < off) rd[k] += rd[k + off]; __syncthreads(); }
    if (k == 0) d_z2[b] = rd[0];
}

// ---------------- final: Cholesky + fused forward solve + loss assembly ----------------
__global__ __launch_bounds__(512) void k_final(const float* __restrict__ vlv,
                        const float* __restrict__ lss_ptr,
                        float* __restrict__ out) {
    extern __shared__ float smf[];
    float* Mm = smf;                 // 128 x 129
    float* R  = smf + 128 * 129;     // 128 x 129: R[i*129+b] = u[b][i] being solved
    __shared__ float sD[128];
    __shared__ float s_diag, s_inv;
    __shared__ double s_ld;
    __shared__ double red[512];
    int t = threadIdx.x;
    float lss = *lss_ptr;
    float var = expf(lss);
    float ivar = 1.f / var;
    if (t < 128) sD[t] = expf(0.5f * vlv[t]);
    if (t == 0) s_ld = 0.0;
    __syncthreads();
    for (int idx = t; idx < 128 * 128; idx += 512) {
        int i = idx >> 7, j = idx & 127;
        float m = sD[i] * d_WtW[idx] * sD[j] * ivar;
        if (i == j) m += 1.f;
        Mm[i * 129 + j] = m;
    }
    for (int idx = t; idx < 128 * 128; idx += 512) {
        int b = idx >> 7, i = idx & 127;
        R[i * 129 + b] = d_u[idx];   // coalesced read of d_u[b*128+i]
    }
    __syncthreads();

    float qacc = 0.f;                // thread t<128 owns batch b = t
    int g = t >> 7, c = t & 127;
    for (int k = 0; k < 128; k++) {
        if (t == 0) {
            float dv = sqrtf(Mm[k * 129 + k]);
            s_diag = dv; s_inv = 1.f / dv;
            s_ld += 2.0 * log((double)dv);
        }
        __syncthreads();
        float inv = s_inv;
        for (int i = k + 1 + t; i < 128; i += 512) Mm[i * 129 + k] *= inv;
        if (t < 128) {
            float y = R[k * 129 + t] * inv;
            R[k * 129 + t] = y;
            qacc = fmaf(y, y, qacc);
        }
        __syncthreads();
        for (int i = k + 1 + g; i < 128; i += 4) {
            float lik = Mm[i * 129 + k];
            if (c > k) Mm[i * 129 + c] -= lik * Mm[c * 129 + k];
            R[i * 129 + c] -= lik * R[k * 129 + c];
        }
        __syncthreads();
    }

    double acc = 0.0;
    if (t < 128) {
        int b = t;
        float quad = (d_eta2[b] - 2.f * d_zg[b] + d_zWz[b]) * ivar - qacc * ivar * ivar;
        double logdet = (double)DM1 * (double)lss + s_ld;
        double ll = -0.5 * ((double)DM1 * LOG2PI + logdet + (double)quad);
        acc = ll + d_mult[b] - 0.5 * (double)d_z2[b] / 128.0;
    }
    red[t] = acc;
    __syncthreads();
    for (int off = 256; off; off >>= 1) { if (t < off) red[t] += red[t + off]; __syncthreads(); }
    if (t == 0) {
        double total = red[0] / 128.0 - 0.5 * LOG2PI;
        out[0] = (float)(-total);
    }
}

// ---------------- launcher ----------------
extern "C" void kernel_launch(void* const* d_in, const int* in_sizes, int n_in,
                              void* d_out, int out_size) {
    const float* x     = (const float*)d_in[0];
    const int*   rows  = (const int*)  d_in[1];
    const int*   cols  = (const int*)  d_in[2];
    const float* vals  = (const float*)d_in[3];
    const float* enc_w = (const float*)d_in[4];
    const float* dec_w = (const float*)d_in[5];
    const float* vlv   = (const float*)d_in[6];
    const float* lss   = (const float*)d_in[7];
    const float* eta   = (const float*)d_in[8];
    int nnz = in_sizes[1];
    float* out = (float*)d_out;

    void *p_dlt, *p_z, *p_g, *p_w, *p_e2;
    cudaGetSymbolAddress(&p_dlt, d_dlt);
    cudaGetSymbolAddress(&p_z,   d_z);
    cudaGetSymbolAddress(&p_g,   d_g);
    cudaGetSymbolAddress(&p_w,   d_WtW);
    cudaGetSymbolAddress(&p_e2,  d_eta2);
    cudaMemsetAsync(p_dlt, 0, (size_t)BB * (DD + 1) * sizeof(float));
    cudaMemsetAsync(p_z,   0, BB * HID * sizeof(float));
    cudaMemsetAsync(p_g,   0, BB * HID * sizeof(float));
    cudaMemsetAsync(p_w,   0, HID * HID * sizeof(float));
    cudaMemsetAsync(p_e2,  0, BB * sizeof(float));

    k_tables<<<1, 32>>>();
    k_meta<<<(DM1 + 255) / 256, 256>>>(rows, cols, vals, nnz);
    k_scan_lx<<<BB, 512>>>(x);

    int nblk = (DM1 + JC - 1) / JC;
    k_gemm_z<<<nblk, 256>>>(enc_w);
    k_gemm_gw<<<nblk, 256>>>(eta, dec_w);
    k_mult<<<BB, 512>>>(x);
    k_uquad<<<BB, 128>>>(vlv);

    cudaFuncSetAttribute(k_final, cudaFuncAttributeMaxDynamicSharedMemorySize,
                         2 * 128 * 129 * (int)sizeof(float));
    k_final<<<1, 512, 2 * 128 * 129 * sizeof(float)>>>(vlv, lss, out);
}

// round 3
// speedup vs baseline: 2.5150x; 1.5867x over previous
#include <cuda_runtime.h>
#include <cuda_bf16.h>
#include <math.h>

#define BB   128
#define DD   20000
#define DM1  19999
#define HID  128
#define ST   20032     // padded bf16 hx row stride (multiple of 64)
#define JC   128
#define NBLK 157       // ceil(DM1/JC)
#define KS   64
#define LDA  74        // bf16 smem row stride (37 words)
#define LOG2PI 1.8378770664093453

// ---------------- device scratch ----------------
__device__ float  d_Pf[(size_t)BB * (DD + 1)];
__device__ float  d_dlt[(size_t)BB * (DD + 1)];
__device__ __nv_bfloat16 d_hxb[(size_t)BB * ST];
__device__ float  d_z[BB * HID];
__device__ float  d_g[BB * HID];
__device__ float  d_WtW[HID * HID];
__device__ float  d_u[BB * HID];
__device__ int    d_lo[DM1], d_mid[DM1], d_hi[DM1];
__device__ float  d_av[DM1], d_bv[DM1];
__device__ double d_sumx[BB], d_sumlg[BB], d_mult[BB];
__device__ float  d_eta2[BB];
__device__ float  d_zg[BB], d_zWz[BB], d_z2[BB];
__device__ double d_lxtab[32];
__device__ double d_lgtab[32];

// ---------------- meta (+ tables) ----------------
__device__ __forceinline__ int lower_bound_i(const int* a, int n, int key) {
    int lo = 0, hi = n;
    while (lo < hi) { int m = (lo + hi) >> 1; if (a[m] < key) lo = m + 1; else hi = m; }
    return lo;
}

__global__ void k_meta(const int* __restrict__ rows, const int* __restrict__ cols,
                       const float* __restrict__ vals, int nnz) {
    int r = blockIdx.x * blockDim.x + threadIdx.x;
    if (blockIdx.x == 0 && threadIdx.x < 32) {
        d_lxtab[threadIdx.x] = log((double)threadIdx.x + 1.0);
        d_lgtab[threadIdx.x] = lgamma((double)threadIdx.x + 1.0);
    }
    if (r >= DM1) return;
    int s = lower_bound_i(rows, nnz, r);
    int e = lower_bound_i(rows, nnz, r + 1);
    d_lo[r] = cols[s];
    d_hi[r] = cols[e - 1] + 1;
    d_av[r] = vals[s];
    d_bv[r] = vals[e - 1];
    int a = s, b = e;
    while (a < b) { int m = (a + b) >> 1; if (vals[m] < 0.f) b = m; else a = m + 1; }
    d_mid[r] = cols[a];
}

// ---------------- prefix scan of log(x+1) ----------------
__global__ __launch_bounds__(512) void k_scan_lx(const float* __restrict__ x) {
    int b = blockIdx.x, t = threadIdx.x, lane = t & 31, wid = t >> 5;
    const float* xb = x + (size_t)b * DD;
    float* Pb = d_Pf + (size_t)b * (DD + 1);
    __shared__ double wtot[16], woff[16];
    __shared__ double s_lx[32];
    __shared__ float  s_lg[32];
    __shared__ float  redf[16];
    if (t < 32) { s_lx[t] = d_lxtab[t]; s_lg[t] = (float)d_lgtab[t]; }
    __syncthreads();

    double carry = 0.0;
    float sx = 0.f, slg = 0.f;
    if (t == 0) Pb[0] = 0.f;

    for (int base = 0; base < DD; base += 4096) {
        double loc[8]; double run = 0.0;
        int i0 = base + t * 8;
        #pragma unroll
        for (int v = 0; v < 8; v++) {
            int i = i0 + v;
            if (i < DD) {
                float xv = xb[i];
                int xi = (int)xv;
                double lv; float lg;
                if (xi >= 0 && xi < 32 && (float)xi == xv) { lv = s_lx[xi]; lg = s_lg[xi]; }
                else { lv = (double)logf(xv + 1.f); lg = lgammaf(xv + 1.f); }
                sx += xv; slg += lg; run += lv;
            }
            loc[v] = run;
        }
        double v = run;
        #pragma unroll
        for (int off = 1; off < 32; off <<= 1) {
            double nv = __shfl_up_sync(0xffffffffu, v, off);
            if (lane >= off) v += nv;
        }
        if (lane == 31) wtot[wid] = v;
        __syncthreads();
        if (wid == 0) {
            double w = (lane < 16) ? wtot[lane] : 0.0;
            #pragma unroll
            for (int off = 1; off < 16; off <<= 1) {
                double nv = __shfl_up_sync(0xffffffffu, w, off);
                if (lane >= off) w += nv;
            }
            if (lane < 16) woff[lane] = w;
        }
        __syncthreads();
        double basd = carry + (wid > 0 ? woff[wid - 1] : 0.0) + (v - run);
        #pragma unroll
        for (int u = 0; u < 8; u++) {
            int i = i0 + u;
            if (i < DD) Pb[i + 1] = (float)(basd + loc[u]);
        }
        carry += woff[15];
        __syncthreads();
    }
    #pragma unroll
    for (int off = 16; off; off >>= 1) sx += __shfl_down_sync(0xffffffffu, sx, off);
    if (lane == 0) redf[wid] = sx;
    __syncthreads();
    if (t == 0) { double s = 0.0; for (int i = 0; i < 16; i++) s += (double)redf[i]; d_sumx[b] = s; }
    __syncthreads();
    #pragma unroll
    for (int off = 16; off; off >>= 1) slg += __shfl_down_sync(0xffffffffu, slg, off);
    if (lane == 0) redf[wid] = slg;
    __syncthreads();
    if (t == 0) { double s = 0.0; for (int i = 0; i < 16; i++) s += (double)redf[i]; d_sumlg[b] = s; }
}

// ---------------- hx -> bf16 (padded) ----------------
__global__ void k_hxb() {
    int j = blockIdx.x * 256 + threadIdx.x;
    int b = blockIdx.y;
    if (j >= ST) return;
    float hv = 0.f;
    if (j < DM1) {
        const float* Pb = d_Pf + (size_t)b * (DD + 1);
        float pl = Pb[d_lo[j]], pm = Pb[d_mid[j]], ph = Pb[d_hi[j]];
        hv = d_av[j] * (pm - pl) + d_bv[j] * (ph - pm);
    }
    d_hxb[(size_t)b * ST + j] = __float2bfloat16(hv);
}

// ---------------- mma helper ----------------
__device__ __forceinline__ void mma_bf16(float* c, unsigned a0, unsigned a1, unsigned a2,
                                         unsigned a3, unsigned b0, unsigned b1) {
    asm volatile("mma.sync.aligned.m16n8k16.row.col.f32.bf16.bf16.f32 "
                 "{%0,%1,%2,%3}, {%4,%5,%6,%7}, {%8,%9}, {%0,%1,%2,%3};\n"
                 : "+f"(c[0]), "+f"(c[1]), "+f"(c[2]), "+f"(c[3])
                 : "r"(a0), "r"(a1), "r"(a2), "r"(a3), "r"(b0), "r"(b1));
}

// ---------------- GEMM z = hx @ enc^T (tensor, split-K) ----------------
__global__ __launch_bounds__(256, 2) void k_gemm_z(const float* __restrict__ enc) {
    __shared__ __nv_bfloat16 As[128 * LDA];
    __shared__ __nv_bfloat16 Bs[128 * LDA];
    int j0 = blockIdx.x * JC, jend = min(j0 + JC, DM1);
    int t = threadIdx.x, lane = t & 31, w = t >> 5;
    int wm = w & 1, wn = w >> 1;
    float acc[4][4][4];
    #pragma unroll
    for (int a = 0; a < 4; a++)
        #pragma unroll
        for (int b = 0; b < 4; b++)
            #pragma unroll
            for (int c = 0; c < 4; c++) acc[a][b][c] = 0.f;

    for (int js = j0; js < jend; js += KS) {
        #pragma unroll
        for (int m = 0; m < 16; m++) {
            int row = w + 8 * m;
            unsigned v = *(const unsigned*)(d_hxb + (size_t)row * ST + js + 2 * lane);
            *(unsigned*)&As[row * LDA + 2 * lane] = v;
        }
        #pragma unroll
        for (int m = 0; m < 16; m++) {
            int n = w + 8 * m;
            int j1 = js + lane, j2 = js + 32 + lane;
            float f1 = (j1 < jend) ? enc[(size_t)n * DM1 + j1] : 0.f;
            float f2 = (j2 < jend) ? enc[(size_t)n * DM1 + j2] : 0.f;
            Bs[n * LDA + lane]      = __float2bfloat16(f1);
            Bs[n * LDA + 32 + lane] = __float2bfloat16(f2);
        }
        __syncthreads();
        #pragma unroll
        for (int kk = 0; kk < 4; kk++) {
            int kb = kk * 16;
            unsigned a[4][4], b[4][2];
            #pragma unroll
            for (int mt = 0; mt < 4; mt++) {
                int r = wm * 64 + mt * 16 + (lane >> 2);
                int co = kb + 2 * (lane & 3);
                a[mt][0] = *(const unsigned*)&As[r * LDA + co];
                a[mt][1] = *(const unsigned*)&As[(r + 8) * LDA + co];
                a[mt][2] = *(const unsigned*)&As[r * LDA + co + 8];
                a[mt][3] = *(const unsigned*)&As[(r + 8) * LDA + co + 8];
            }
            #pragma unroll
            for (int nt = 0; nt < 4; nt++) {
                int n = wn * 32 + nt * 8 + (lane >> 2);
                int co = kb + 2 * (lane & 3);
                b[nt][0] = *(const unsigned*)&Bs[n * LDA + co];
                b[nt][1] = *(const unsigned*)&Bs[n * LDA + co + 8];
            }
            #pragma unroll
            for (int mt = 0; mt < 4; mt++)
                #pragma unroll
                for (int nt = 0; nt < 4; nt++)
                    mma_bf16(acc[mt][nt], a[mt][0], a[mt][1], a[mt][2], a[mt][3],
                             b[nt][0], b[nt][1]);
        }
        __syncthreads();
    }
    #pragma unroll
    for (int mt = 0; mt < 4; mt++)
        #pragma unroll
        for (int nt = 0; nt < 4; nt++) {
            int r = wm * 64 + mt * 16 + (lane >> 2);
            int c = wn * 32 + nt * 8 + 2 * (lane & 3);
            atomicAdd(&d_z[r * HID + c],           acc[mt][nt][0]);
            atomicAdd(&d_z[r * HID + c + 1],       acc[mt][nt][1]);
            atomicAdd(&d_z[(r + 8) * HID + c],     acc[mt][nt][2]);
            atomicAdd(&d_z[(r + 8) * HID + c + 1], acc[mt][nt][3]);
        }
}

// ---- fused: g = eta @ dec_w, WtW = dec^T dec (tensor) + logits scatter ----
__global__ __launch_bounds__(256, 1) void k_gemm_gw(const float* __restrict__ eta,
                                                    const float* __restrict__ dw) {
    __shared__ __nv_bfloat16 Et[128 * LDA];
    __shared__ __nv_bfloat16 Dt[128 * LDA];
    __shared__ int   slo[JC], smi[JC], shi[JC];
    __shared__ float sa[JC], sb[JC];
    int j0 = blockIdx.x * JC, jend = min(j0 + JC, DM1);
    int t = threadIdx.x, lane = t & 31, w = t >> 5;
    int wm = w & 1, wn = w >> 1;
    if (t < JC) {
        int j = j0 + t;
        if (j < jend) {
            slo[t] = d_lo[j]; smi[t] = d_mid[j]; shi[t] = d_hi[j];
            sa[t] = d_av[j];  sb[t] = d_bv[j];
        }
    }
    __syncthreads();
    float accg[4][4][4], accw[4][4][4];
    #pragma unroll
    for (int a = 0; a < 4; a++)
        #pragma unroll
        for (int b = 0; b < 4; b++)
            #pragma unroll
            for (int c = 0; c < 4; c++) { accg[a][b][c] = 0.f; accw[a][b][c] = 0.f; }

    for (int js = j0; js < jend; js += KS) {
        #pragma unroll
        for (int m = 0; m < 16; m++) {
            int b = w + 8 * m;
            #pragma unroll
            for (int h = 0; h < 2; h++) {
                int j = js + 32 * h + lane;
                float e = 0.f;
                if (j < jend) {
                    e = eta[(size_t)b * DM1 + j];
                    int jl = j - j0;
                    float a = sa[jl], bb = sb[jl];
                    float* dp = d_dlt + (size_t)b * (DD + 1);
                    atomicAdd(dp + slo[jl], a * e);
                    atomicAdd(dp + smi[jl], (bb - a) * e);
                    atomicAdd(dp + shi[jl], -bb * e);
                }
                Et[b * LDA + 32 * h + lane] = __float2bfloat16(e);
            }
        }
        #pragma unroll
        for (int pp = 0; pp < 8; pp++) {
            int jj = js + pp * 8 + w;
            float4 v = make_float4(0.f, 0.f, 0.f, 0.f);
            if (jj < jend) v = *(const float4*)(dw + (size_t)jj * HID + 4 * lane);
            int jl = jj - js;
            Dt[(4 * lane + 0) * LDA + jl] = __float2bfloat16(v.x);
            Dt[(4 * lane + 1) * LDA + jl] = __float2bfloat16(v.y);
            Dt[(4 * lane + 2) * LDA + jl] = __float2bfloat16(v.z);
            Dt[(4 * lane + 3) * LDA + jl] = __float2bfloat16(v.w);
        }
        __syncthreads();
        #pragma unroll
        for (int kk = 0; kk < 4; kk++) {
            int kb = kk * 16;
            int co = kb + 2 * (lane & 3);
            unsigned aE[4][4], aD[4][4], bD[4][2];
            #pragma unroll
            for (int mt = 0; mt < 4; mt++) {
                int r = wm * 64 + mt * 16 + (lane >> 2);
                aE[mt][0] = *(const unsigned*)&Et[r * LDA + co];
                aE[mt][1] = *(const unsigned*)&Et[(r + 8) * LDA + co];
                aE[mt][2] = *(const unsigned*)&Et[r * LDA + co + 8];
                aE[mt][3] = *(const unsigned*)&Et[(r + 8) * LDA + co + 8];
                aD[mt][0] = *(const unsigned*)&Dt[r * LDA + co];
                aD[mt][1] = *(const unsigned*)&Dt[(r + 8) * LDA + co];
                aD[mt][2] = *(const unsigned*)&Dt[r * LDA + co + 8];
                aD[mt][3] = *(const unsigned*)&Dt[(r + 8) * LDA + co + 8];
            }
            #pragma unroll
            for (int nt = 0; nt < 4; nt++) {
                int n = wn * 32 + nt * 8 + (lane >> 2);
                bD[nt][0] = *(const unsigned*)&Dt[n * LDA + co];
                bD[nt][1] = *(const unsigned*)&Dt[n * LDA + co + 8];
            }
            #pragma unroll
            for (int mt = 0; mt < 4; mt++)
                #pragma unroll
                for (int nt = 0; nt < 4; nt++) {
                    mma_bf16(accg[mt][nt], aE[mt][0], aE[mt][1], aE[mt][2], aE[mt][3],
                             bD[nt][0], bD[nt][1]);
                    mma_bf16(accw[mt][nt], aD[mt][0], aD[mt][1], aD[mt][2], aD[mt][3],
                             bD[nt][0], bD[nt][1]);
                }
        }
        __syncthreads();
    }
    #pragma unroll
    for (int mt = 0; mt < 4; mt++)
        #pragma unroll
        for (int nt = 0; nt < 4; nt++) {
            int r = wm * 64 + mt * 16 + (lane >> 2);
            int c = wn * 32 + nt * 8 + 2 * (lane & 3);
            atomicAdd(&d_g[r * HID + c],           accg[mt][nt][0]);
            atomicAdd(&d_g[r * HID + c + 1],       accg[mt][nt][1]);
            atomicAdd(&d_g[(r + 8) * HID + c],     accg[mt][nt][2]);
            atomicAdd(&d_g[(r + 8) * HID + c + 1], accg[mt][nt][3]);
            atomicAdd(&d_WtW[r * HID + c],           accw[mt][nt][0]);
            atomicAdd(&d_WtW[r * HID + c + 1],       accw[mt][nt][1]);
            atomicAdd(&d_WtW[(r + 8) * HID + c],     accw[mt][nt][2]);
            atomicAdd(&d_WtW[(r + 8) * HID + c + 1], accw[mt][nt][3]);
        }
}

// ---------------- logits scan + multinomial logprob ----------------
__global__ __launch_bounds__(512) void k_mult(const float* __restrict__ x) {
    int b = blockIdx.x, t = threadIdx.x, lane = t & 31, wid = t >> 5;
    const float* xb = x + (size_t)b * DD;
    const float* db = d_dlt + (size_t)b * (DD + 1);
    __shared__ float wtot[16], woff[16];
    __shared__ float redf[16];
    float carry = 0.f, sexp = 0.f, sxl = 0.f;

    for (int base = 0; base < DD; base += 4096) {
        float loc[8], xv[8]; float run = 0.f;
        int i0 = base + t * 8;
        #pragma unroll
        for (int v = 0; v < 8; v++) {
            int i = i0 + v;
            float dv = (i < DD) ? db[i] : 0.f;
            xv[v] = (i < DD) ? xb[i] : 0.f;
            run += dv;
            loc[v] = run;
        }
        float v = run;
        #pragma unroll
        for (int off = 1; off < 32; off <<= 1) {
            float nv = __shfl_up_sync(0xffffffffu, v, off);
            if (lane >= off) v += nv;
        }
        if (lane == 31) wtot[wid] = v;
        __syncthreads();
        if (wid == 0) {
            float w = (lane < 16) ? wtot[lane] : 0.f;
            #pragma unroll
            for (int off = 1; off < 16; off <<= 1) {
                float nv = __shfl_up_sync(0xffffffffu, w, off);
                if (lane >= off) w += nv;
            }
            if (lane < 16) woff[lane] = w;
        }
        __syncthreads();
        float basf = carry + (wid > 0 ? woff[wid - 1] : 0.f) + (v - run);
        #pragma unroll
        for (int u = 0; u < 8; u++) {
            int i = i0 + u;
            if (i < DD) {
                float logit = basf + loc[u];
                sexp += expf(logit);
                sxl = fmaf(xv[u], logit, sxl);
            }
        }
        carry += woff[15];
        __syncthreads();
    }
    #pragma unroll
    for (int off = 16; off; off >>= 1) sexp += __shfl_down_sync(0xffffffffu, sexp, off);
    if (lane == 0) redf[wid] = sexp;
    __syncthreads();
    double tsexp = 0.0;
    if (t == 0) { for (int i = 0; i < 16; i++) tsexp += (double)redf[i]; }
    __syncthreads();
    #pragma unroll
    for (int off = 16; off; off >>= 1) sxl += __shfl_down_sync(0xffffffffu, sxl, off);
    if (lane == 0) redf[wid] = sxl;
    __syncthreads();
    if (t == 0) {
        double s = 0.0; for (int i = 0; i < 16; i++) s += (double)redf[i];
        double sx = d_sumx[b];
        d_mult[b] = lgamma(sx + 1.0) - d_sumlg[b] + s - sx * log(tsexp);
    }
}

// ---------------- u = (g - z@WtW)*sD, quad pieces, eta^2 ----------------
__global__ void k_uquad(const float* __restrict__ vlv, const float* __restrict__ eta) {
    int b = blockIdx.x, k = threadIdx.x;
    __shared__ float zs[128];
    __shared__ float rd[128];
    float s = 0.f;
    for (int j = k; j < DM1; j += 128) { float e = eta[(size_t)b * DM1 + j]; s = fmaf(e, e, s); }
    rd[k] = s; __syncthreads();
    for (int off = 64; off; off >>= 1) { if (k < off) rd[k] += rd[k + off]; __syncthreads(); }
    if (k == 0) d_eta2[b] = rd[0];
    __syncthreads();

    zs[k] = d_z[b * HID + k];
    __syncthreads();
    float wv = 0.f;
    #pragma unroll 8
    for (int k2 = 0; k2 < 128; k2++) wv = fmaf(zs[k2], d_WtW[k2 * HID + k], wv);
    float g = d_g[b * HID + k];
    float sd = expf(0.5f * vlv[k]);
    d_u[b * HID + k] = (g - wv) * sd;
    float z = zs[k];

    rd[k] = z * g; __syncthreads();
    for (int off = 64; off; off >>= 1) { if (k < off) rd[k] += rd[k + off]; __syncthreads(); }
    if (k == 0) d_zg[b] = rd[0];
    __syncthreads();
    rd[k] = z * wv; __syncthreads();
    for (int off = 64; off; off >>= 1) { if (k < off) rd[k] += rd[k + off]; __syncthreads(); }
    if (k == 0) d_zWz[b] = rd[0];
    __syncthreads();
    rd[k] = z * z; __syncthreads();
    for (int off = 64; off; off >>= 1) { if (k < off) rd[k] += rd[k + off]; __syncthreads(); }
    if (k == 0) d_z2[b] = rd[0];
}

// ---------------- final: panel Cholesky + solve + loss ----------------
__global__ __launch_bounds__(512) void k_final(const float* __restrict__ vlv,
                                               const float* __restrict__ lss_ptr,
                                               float* __restrict__ out) {
    extern __shared__ float smf[];
    float* Mm = smf;                 // 128 x 129
    float* R  = smf + 128 * 129;     // 128 x 129: R[i*129+b]
    __shared__ __align__(16) float Lp[120 * 8];
    __shared__ float sinv[8];
    __shared__ float sD[128];
    __shared__ double s_ld;
    __shared__ double red[512];
    int t = threadIdx.x, lane = t & 31;
    float lss = *lss_ptr;
    float var = expf(lss);
    float ivar = 1.f / var;
    if (t < 128) sD[t] = expf(0.5f * vlv[t]);
    __syncthreads();
    for (int idx = t; idx < 128 * 128; idx += 512) {
        int i = idx >> 7, j = idx & 127;
        float m = sD[i] * d_WtW[idx] * sD[j] * ivar;
        if (i == j) m += 1.f;
        Mm[i * 129 + j] = m;
    }
    for (int idx = t; idx < 128 * 128; idx += 512) {
        int b = idx >> 7, i = idx & 127;
        R[i * 129 + b] = d_u[idx];
    }
    __syncthreads();

    float qacc = 0.f;      // threads 256..383 own b = t-256
    double ldacc = 0.0;    // warp 0

    for (int p = 0; p < 16; p++) {
        int k0 = 8 * p;
        // S1: warp 0 factors 8x8 diag block via shuffles
        if (t < 32) {
            int r = lane & 7;
            float v[8];
            #pragma unroll
            for (int c = 0; c < 8; c++) v[c] = Mm[(k0 + r) * 129 + k0 + c];
            #pragma unroll
            for (int kk = 0; kk < 8; kk++) {
                float dkk = __shfl_sync(0xffffffffu, v[kk], kk);
                float d = sqrtf(dkk);
                float inv = 1.f / d;
                if (lane == kk) { v[kk] = d; ldacc += 2.0 * log((double)d); }
                if (r > kk && lane != kk) v[kk] *= inv;
                #pragma unroll
                for (int c = kk + 1; c < 8; c++) {
                    float Lck = __shfl_sync(0xffffffffu, v[kk], c);
                    if (r > kk) v[c] -= v[kk] * Lck;
                }
            }
            if (lane < 8) {
                #pragma unroll
                for (int c = 0; c < 8; c++) Mm[(k0 + r) * 129 + k0 + c] = v[c];
                sinv[r] = 1.f / v[r];
            }
        }
        __syncthreads();

        // S2: panel below-diag solve + R forward solve
        int nrem = 120 - k0;
        if (t < nrem) {
            int i = k0 + 8 + t;
            float a[8];
            #pragma unroll
            for (int c = 0; c < 8; c++) a[c] = Mm[i * 129 + k0 + c];
            #pragma unroll
            for (int c = 0; c < 8; c++) {
                float s = a[c];
                #pragma unroll
                for (int q = 0; q < 8; q++) if (q < c) s -= a[q] * Mm[(k0 + c) * 129 + k0 + q];
                a[c] = s * sinv[c];
            }
            #pragma unroll
            for (int c = 0; c < 8; c++) { Mm[i * 129 + k0 + c] = a[c]; Lp[t * 8 + c] = a[c]; }
        } else if (t >= 256 && t < 384) {
            int b = t - 256;
            float y[8];
            #pragma unroll
            for (int c = 0; c < 8; c++) y[c] = R[(k0 + c) * 129 + b];
            #pragma unroll
            for (int c = 0; c < 8; c++) {
                float s = y[c];
                #pragma unroll
                for (int q = 0; q < 8; q++) if (q < c) s -= y[q] * Mm[(k0 + c) * 129 + k0 + q];
                y[c] = s * sinv[c];
                qacc = fmaf(y[c], y[c], qacc);
            }
            #pragma unroll
            for (int c = 0; c < 8; c++) R[(k0 + c) * 129 + b] = y[c];
        }
        __syncthreads();

        // S3: trailing updates (Mm full-square rank-8, R rank-8)
        int base = k0 + 8, n = 128 - base;
        if (n > 0) {
            int io = t & 127, jg = t >> 7;
            if (io < n) {
                int i = base + io;
                float Li[8];
                #pragma unroll
                for (int q = 0; q < 8; q++) Li[q] = Lp[io * 8 + q];
                for (int jo = jg; jo < n; jo += 4) {
                    int j = base + jo;
                    const float4* lp4 = (const float4*)&Lp[jo * 8];
                    float4 L0 = lp4[0], L1 = lp4[1];
                    float s = Mm[i * 129 + j];
                    s -= Li[0] * L0.x + Li[1] * L0.y + Li[2] * L0.z + Li[3] * L0.w
                       + Li[4] * L1.x + Li[5] * L1.y + Li[6] * L1.z + Li[7] * L1.w;
                    Mm[i * 129 + j] = s;
                }
            }
            {
                int b = t & 127, ig = t >> 7;
                float y[8];
                #pragma unroll
                for (int q = 0; q < 8; q++) y[q] = R[(k0 + q) * 129 + b];
                for (int io2 = ig; io2 < n; io2 += 4) {
                    int i = base + io2;
                    const float4* lp4 = (const float4*)&Lp[io2 * 8];
                    float4 L0 = lp4[0], L1 = lp4[1];
                    float s = R[i * 129 + b];
                    s -= y[0] * L0.x + y[1] * L0.y + y[2] * L0.z + y[3] * L0.w
                       + y[4] * L1.x + y[5] * L1.y + y[6] * L1.z + y[7] * L1.w;
                    R[i * 129 + b] = s;
                }
            }
        }
        __syncthreads();
    }

    if (t < 32) {
        #pragma unroll
        for (int off = 16; off; off >>= 1) ldacc += __shfl_down_sync(0xffffffffu, ldacc, off);
        if (lane == 0) s_ld = ldacc;
    }
    __syncthreads();

    double acc = 0.0;
    if (t >= 256 && t < 384) {
        int b = t - 256;
        float quad = (d_eta2[b] - 2.f * d_zg[b] + d_zWz[b]) * ivar - qacc * ivar * ivar;
        double logdet = (double)DM1 * (double)lss + s_ld;
        double ll = -0.5 * ((double)DM1 * LOG2PI + logdet + (double)quad);
        acc = ll + d_mult[b] - 0.5 * (double)d_z2[b] / 128.0;
    }
    red[t] = acc;
    __syncthreads();
    for (int off = 256; off; off >>= 1) { if (t < off) red[t] += red[t + off]; __syncthreads(); }
    if (t == 0) {
        double total = red[0] / 128.0 - 0.5 * LOG2PI;
        out[0] = (float)(-total);
    }
}

// ---------------- launcher ----------------
extern "C" void kernel_launch(void* const* d_in, const int* in_sizes, int n_in,
                              void* d_out, int out_size) {
    const float* x     = (const float*)d_in[0];
    const int*   rows  = (const int*)  d_in[1];
    const int*   cols  = (const int*)  d_in[2];
    const float* vals  = (const float*)d_in[3];
    const float* enc_w = (const float*)d_in[4];
    const float* dec_w = (const float*)d_in[5];
    const float* vlv   = (const float*)d_in[6];
    const float* lss   = (const float*)d_in[7];
    const float* eta   = (const float*)d_in[8];
    int nnz = in_sizes[1];
    float* out = (float*)d_out;

    void *p_dlt, *p_z, *p_g, *p_w;
    cudaGetSymbolAddress(&p_dlt, d_dlt);
    cudaGetSymbolAddress(&p_z,   d_z);
    cudaGetSymbolAddress(&p_g,   d_g);
    cudaGetSymbolAddress(&p_w,   d_WtW);
    cudaMemsetAsync(p_dlt, 0, (size_t)BB * (DD + 1) * sizeof(float));
    cudaMemsetAsync(p_z,   0, BB * HID * sizeof(float));
    cudaMemsetAsync(p_g,   0, BB * HID * sizeof(float));
    cudaMemsetAsync(p_w,   0, HID * HID * sizeof(float));

    k_meta<<<(DM1 + 255) / 256, 256>>>(rows, cols, vals, nnz);
    k_scan_lx<<<BB, 512>>>(x);

    dim3 ghx((ST + 255) / 256, BB);
    k_hxb<<<ghx, 256>>>();
    k_gemm_gw<<<NBLK, 256>>>(eta, dec_w);
    k_gemm_z<<<NBLK, 256>>>(enc_w);
    k_mult<<<BB, 512>>>(x);
    k_uquad<<<BB, 128>>>(vlv, eta);

    cudaFuncSetAttribute(k_final, cudaFuncAttributeMaxDynamicSharedMemorySize,
                         2 * 128 * 129 * (int)sizeof(float));
    k_final<<<1, 512, 2 * 128 * 129 * sizeof(float)>>>(vlv, lss, out);
}

// round 4
// speedup vs baseline: 2.6048x; 1.0357x over previous
#include <cuda_runtime.h>
#include <cuda_bf16.h>
#include <math.h>

#define BB   128
#define DD   20000
#define DM1  19999
#define HID  128
#define ST   20224     // padded bf16 row stride = 79*256
#define JC2  256
#define NBLK2 79
#define LDA  74
#define LOG2PI 1.8378770664093453

// ---------------- device scratch ----------------
__device__ float  d_Pf[(size_t)BB * (DD + 1)];
__device__ float  d_dlt[(size_t)BB * (DD + 1)];
__device__ __nv_bfloat16 d_hxb[(size_t)BB * ST];
__device__ __nv_bfloat16 d_encb[(size_t)HID * ST];
__device__ __nv_bfloat16 d_etab[(size_t)BB * ST];
__device__ __nv_bfloat16 d_dect[(size_t)HID * ST];
__device__ float  d_z[BB * HID];
__device__ float  d_g[BB * HID];
__device__ float  d_WtW[HID * HID];
__device__ float  d_u[BB * HID];
__device__ int    d_lo[DM1], d_mid[DM1], d_hi[DM1];
__device__ float  d_av[DM1], d_bv[DM1];
__device__ double d_sumx[BB], d_sumlg[BB], d_mult[BB];
__device__ float  d_eta2[BB];
__device__ float  d_zg[BB], d_zWz[BB], d_z2[BB];

// ---------------- meta ----------------
__device__ __forceinline__ int lower_bound_i(const int* a, int n, int key) {
    int lo = 0, hi = n;
    while (lo < hi) { int m = (lo + hi) >> 1; if (a[m] < key) lo = m + 1; else hi = m; }
    return lo;
}

__global__ void k_meta(const int* __restrict__ rows, const int* __restrict__ cols,
                       const float* __restrict__ vals, int nnz) {
    int r = blockIdx.x * blockDim.x + threadIdx.x;
    if (r >= DM1) return;
    int s = lower_bound_i(rows, nnz, r);
    int e = lower_bound_i(rows, nnz, r + 1);
    d_lo[r] = cols[s];
    d_hi[r] = cols[e - 1] + 1;
    d_av[r] = vals[s];
    d_bv[r] = vals[e - 1];
    int a = s, b = e;
    while (a < b) { int m = (a + b) >> 1; if (vals[m] < 0.f) b = m; else a = m + 1; }
    d_mid[r] = cols[a];
}

// ---------------- prefix scan of log(x+1) ----------------
__global__ __launch_bounds__(512) void k_scan_lx(const float* __restrict__ x) {
    int b = blockIdx.x, t = threadIdx.x, lane = t & 31, wid = t >> 5;
    const float* xb = x + (size_t)b * DD;
    float* Pb = d_Pf + (size_t)b * (DD + 1);
    __shared__ double wtot[16], woff[16];
    __shared__ double s_lx[32];
    __shared__ float  s_lg[32];
    __shared__ float  redf[16];
    if (t < 32) {
        s_lx[t] = log((double)t + 1.0);
        s_lg[t] = (float)lgamma((double)t + 1.0);
    }
    __syncthreads();

    double carry = 0.0;
    float sx = 0.f, slg = 0.f;
    if (t == 0) Pb[0] = 0.f;

    for (int base = 0; base < DD; base += 4096) {
        double loc[8]; double run = 0.0;
        int i0 = base + t * 8;
        #pragma unroll
        for (int v = 0; v < 8; v++) {
            int i = i0 + v;
            if (i < DD) {
                float xv = xb[i];
                int xi = (int)xv;
                double lv; float lg;
                if (xi >= 0 && xi < 32 && (float)xi == xv) { lv = s_lx[xi]; lg = s_lg[xi]; }
                else { lv = (double)logf(xv + 1.f); lg = lgammaf(xv + 1.f); }
                sx += xv; slg += lg; run += lv;
            }
            loc[v] = run;
        }
        double v = run;
        #pragma unroll
        for (int off = 1; off < 32; off <<= 1) {
            double nv = __shfl_up_sync(0xffffffffu, v, off);
            if (lane >= off) v += nv;
        }
        if (lane == 31) wtot[wid] = v;
        __syncthreads();
        if (wid == 0) {
            double w = (lane < 16) ? wtot[lane] : 0.0;
            #pragma unroll
            for (int off = 1; off < 16; off <<= 1) {
                double nv = __shfl_up_sync(0xffffffffu, w, off);
                if (lane >= off) w += nv;
            }
            if (lane < 16) woff[lane] = w;
        }
        __syncthreads();
        double basd = carry + (wid > 0 ? woff[wid - 1] : 0.0) + (v - run);
        #pragma unroll
        for (int u = 0; u < 8; u++) {
            int i = i0 + u;
            if (i < DD) Pb[i + 1] = (float)(basd + loc[u]);
        }
        carry += woff[15];
        __syncthreads();
    }
    #pragma unroll
    for (int off = 16; off; off >>= 1) sx += __shfl_down_sync(0xffffffffu, sx, off);
    if (lane == 0) redf[wid] = sx;
    __syncthreads();
    if (t == 0) { double s = 0.0; for (int i = 0; i < 16; i++) s += (double)redf[i]; d_sumx[b] = s; }
    __syncthreads();
    #pragma unroll
    for (int off = 16; off; off >>= 1) slg += __shfl_down_sync(0xffffffffu, slg, off);
    if (lane == 0) redf[wid] = slg;
    __syncthreads();
    if (t == 0) { double s = 0.0; for (int i = 0; i < 16; i++) s += (double)redf[i]; d_sumlg[b] = s; }
}

// ---------------- hx -> bf16 (padded) ----------------
__global__ void k_hxb() {
    int j = blockIdx.x * 256 + threadIdx.x;
    int b = blockIdx.y;
    if (j >= ST) return;
    float hv = 0.f;
    if (j < DM1) {
        const float* Pb = d_Pf + (size_t)b * (DD + 1);
        float pl = Pb[d_lo[j]], pm = Pb[d_mid[j]], ph = Pb[d_hi[j]];
        hv = d_av[j] * (pm - pl) + d_bv[j] * (ph - pm);
    }
    d_hxb[(size_t)b * ST + j] = __float2bfloat16(hv);
}

// ---------------- enc fp32 -> bf16 padded ----------------
__global__ void k_cvt_enc(const float* __restrict__ enc) {
    int n = blockIdx.y;
    int j = 2 * (blockIdx.x * 256 + threadIdx.x);
    if (j >= ST) return;
    float f1 = (j < DM1)     ? enc[(size_t)n * DM1 + j]     : 0.f;
    float f2 = (j + 1 < DM1) ? enc[(size_t)n * DM1 + j + 1] : 0.f;
    __nv_bfloat162 p = __floats2bfloat162_rn(f1, f2);
    *(unsigned*)&d_encb[(size_t)n * ST + j] = *(unsigned*)&p;
}

// ---------------- eta -> bf16 padded + scatter + eta^2 ----------------
__global__ void k_cvt_eta(const float* __restrict__ eta) {
    int b = blockIdx.y;
    int j = 2 * (blockIdx.x * 256 + threadIdx.x);
    float ex = 0.f, ey = 0.f;
    float* dp = d_dlt + (size_t)b * (DD + 1);
    if (j < DM1) {
        ex = eta[(size_t)b * DM1 + j];
        float a = d_av[j], bb = d_bv[j];
        atomicAdd(dp + d_lo[j],  a * ex);
        atomicAdd(dp + d_mid[j], (bb - a) * ex);
        atomicAdd(dp + d_hi[j], -bb * ex);
    }
    if (j + 1 < DM1) {
        ey = eta[(size_t)b * DM1 + j + 1];
        float a = d_av[j + 1], bb = d_bv[j + 1];
        atomicAdd(dp + d_lo[j + 1],  a * ey);
        atomicAdd(dp + d_mid[j + 1], (bb - a) * ey);
        atomicAdd(dp + d_hi[j + 1], -bb * ey);
    }
    if (j < ST) {
        __nv_bfloat162 p = __floats2bfloat162_rn(ex, ey);
        *(unsigned*)&d_etab[(size_t)b * ST + j] = *(unsigned*)&p;
    }
    float s = fmaf(ex, ex, ey * ey);
    #pragma unroll
    for (int off = 16; off; off >>= 1) s += __shfl_down_sync(0xffffffffu, s, off);
    if ((threadIdx.x & 31) == 0) atomicAdd(&d_eta2[b], s);
}

// ---------------- dec [j][128] fp32 -> dect [n][ST] bf16 ----------------
__global__ __launch_bounds__(256) void k_trans_dec(const float* __restrict__ dw) {
    __shared__ __nv_bfloat16 tile[64][132];
    int j0 = blockIdx.x * 64;
    int t = threadIdx.x;
    #pragma unroll
    for (int p = 0; p < 16; p++) {
        int idx = t + 256 * p;           // over 64*64 float2
        int jj = idx >> 6, c2 = idx & 63;
        int j = j0 + jj;
        float2 v = make_float2(0.f, 0.f);
        if (j < DM1) v = *(const float2*)(dw + (size_t)j * HID + 2 * c2);
        tile[jj][2 * c2]     = __float2bfloat16(v.x);
        tile[jj][2 * c2 + 1] = __float2bfloat16(v.y);
    }
    __syncthreads();
    #pragma unroll
    for (int p = 0; p < 16; p++) {
        int idx = t + 256 * p;           // over 128n * 32 pairs
        int n = idx >> 5, jw = idx & 31;
        __nv_bfloat162 pk;
        pk.x = tile[2 * jw][n];
        pk.y = tile[2 * jw + 1][n];
        *(unsigned*)&d_dect[(size_t)n * ST + j0 + 2 * jw] = *(unsigned*)&pk;
    }
}

// ---------------- mma helper ----------------
__device__ __forceinline__ void mma_bf16(float* c, unsigned a0, unsigned a1, unsigned a2,
                                         unsigned a3, unsigned b0, unsigned b1) {
    asm volatile("mma.sync.aligned.m16n8k16.row.col.f32.bf16.bf16.f32 "
                 "{%0,%1,%2,%3}, {%4,%5,%6,%7}, {%8,%9}, {%0,%1,%2,%3};\n"
                 : "+f"(c[0]), "+f"(c[1]), "+f"(c[2]), "+f"(c[3])
                 : "r"(a0), "r"(a1), "r"(a2), "r"(a3), "r"(b0), "r"(b1));
}

// ---------------- generic 128x128 split-K bf16 GEMM body ----------------
__device__ __forceinline__ void gemm_body(const __nv_bfloat16* __restrict__ A,
                                          const __nv_bfloat16* __restrict__ B,
                                          float* __restrict__ C,
                                          __nv_bfloat16* As, __nv_bfloat16* Bs) {
    int j0 = blockIdx.x * JC2;
    int t = threadIdx.x, lane = t & 31, w = t >> 5;
    int wm = w & 1, wn = w >> 1;
    float acc[4][4][4];
    #pragma unroll
    for (int a = 0; a < 4; a++)
        #pragma unroll
        for (int b = 0; b < 4; b++)
            #pragma unroll
            for (int c = 0; c < 4; c++) acc[a][b][c] = 0.f;

    #pragma unroll
    for (int ch = 0; ch < 4; ch++) {
        int js = j0 + 64 * ch;
        #pragma unroll
        for (int m = 0; m < 16; m++) {
            int row = w + 8 * m;
            unsigned va = *(const unsigned*)(A + (size_t)row * ST + js + 2 * lane);
            *(unsigned*)&As[row * LDA + 2 * lane] = va;
            unsigned vb = *(const unsigned*)(B + (size_t)row * ST + js + 2 * lane);
            *(unsigned*)&Bs[row * LDA + 2 * lane] = vb;
        }
        __syncthreads();
        #pragma unroll
        for (int kk = 0; kk < 4; kk++) {
            int co = kk * 16 + 2 * (lane & 3);
            unsigned a[4][4], b[4][2];
            #pragma unroll
            for (int mt = 0; mt < 4; mt++) {
                int r = wm * 64 + mt * 16 + (lane >> 2);
                a[mt][0] = *(const unsigned*)&As[r * LDA + co];
                a[mt][1] = *(const unsigned*)&As[(r + 8) * LDA + co];
                a[mt][2] = *(const unsigned*)&As[r * LDA + co + 8];
                a[mt][3] = *(const unsigned*)&As[(r + 8) * LDA + co + 8];
            }
            #pragma unroll
            for (int nt = 0; nt < 4; nt++) {
                int n = wn * 32 + nt * 8 + (lane >> 2);
                b[nt][0] = *(const unsigned*)&Bs[n * LDA + co];
                b[nt][1] = *(const unsigned*)&Bs[n * LDA + co + 8];
            }
            #pragma unroll
            for (int mt = 0; mt < 4; mt++)
                #pragma unroll
                for (int nt = 0; nt < 4; nt++)
                    mma_bf16(acc[mt][nt], a[mt][0], a[mt][1], a[mt][2], a[mt][3],
                             b[nt][0], b[nt][1]);
        }
        __syncthreads();
    }
    #pragma unroll
    for (int mt = 0; mt < 4; mt++)
        #pragma unroll
        for (int nt = 0; nt < 4; nt++) {
            int r = wm * 64 + mt * 16 + (lane >> 2);
            int c = wn * 32 + nt * 8 + 2 * (lane & 3);
            atomicAdd(&C[r * HID + c],           acc[mt][nt][0]);
            atomicAdd(&C[r * HID + c + 1],       acc[mt][nt][1]);
            atomicAdd(&C[(r + 8) * HID + c],     acc[mt][nt][2]);
            atomicAdd(&C[(r + 8) * HID + c + 1], acc[mt][nt][3]);
        }
}

__global__ __launch_bounds__(256, 2) void k_gemm_z() {
    __shared__ __nv_bfloat16 As[128 * LDA];
    __shared__ __nv_bfloat16 Bs[128 * LDA];
    gemm_body(d_hxb, d_encb, d_z, As, Bs);
}

__global__ __launch_bounds__(256, 2) void k_gemm_g() {
    __shared__ __nv_bfloat16 As[128 * LDA];
    __shared__ __nv_bfloat16 Bs[128 * LDA];
    gemm_body(d_etab, d_dect, d_g, As, Bs);
}

// WtW: A == B == dect, single smem tile
__global__ __launch_bounds__(256, 2) void k_gemm_w() {
    __shared__ __nv_bfloat16 As[128 * LDA];
    int j0 = blockIdx.x * JC2;
    int t = threadIdx.x, lane = t & 31, w = t >> 5;
    int wm = w & 1, wn = w >> 1;
    float acc[4][4][4];
    #pragma unroll
    for (int a = 0; a < 4; a++)
        #pragma unroll
        for (int b = 0; b < 4; b++)
            #pragma unroll
            for (int c = 0; c < 4; c++) acc[a][b][c] = 0.f;

    #pragma unroll
    for (int ch = 0; ch < 4; ch++) {
        int js = j0 + 64 * ch;
        #pragma unroll
        for (int m = 0; m < 16; m++) {
            int row = w + 8 * m;
            unsigned va = *(const unsigned*)(d_dect + (size_t)row * ST + js + 2 * lane);
            *(unsigned*)&As[row * LDA + 2 * lane] = va;
        }
        __syncthreads();
        #pragma unroll
        for (int kk = 0; kk < 4; kk++) {
            int co = kk * 16 + 2 * (lane & 3);
            unsigned a[4][4], b[4][2];
            #pragma unroll
            for (int mt = 0; mt < 4; mt++) {
                int r = wm * 64 + mt * 16 + (lane >> 2);
                a[mt][0] = *(const unsigned*)&As[r * LDA + co];
                a[mt][1] = *(const unsigned*)&As[(r + 8) * LDA + co];
                a[mt][2] = *(const unsigned*)&As[r * LDA + co + 8];
                a[mt][3] = *(const unsigned*)&As[(r + 8) * LDA + co + 8];
            }
            #pragma unroll
            for (int nt = 0; nt < 4; nt++) {
                int n = wn * 32 + nt * 8 + (lane >> 2);
                b[nt][0] = *(const unsigned*)&As[n * LDA + co];
                b[nt][1] = *(const unsigned*)&As[n * LDA + co + 8];
            }
            #pragma unroll
            for (int mt = 0; mt < 4; mt++)
                #pragma unroll
                for (int nt = 0; nt < 4; nt++)
                    mma_bf16(acc[mt][nt], a[mt][0], a[mt][1], a[mt][2], a[mt][3],
                             b[nt][0], b[nt][1]);
        }
        __syncthreads();
    }
    #pragma unroll
    for (int mt = 0; mt < 4; mt++)
        #pragma unroll
        for (int nt = 0; nt < 4; nt++) {
            int r = wm * 64 + mt * 16 + (lane >> 2);
            int c = wn * 32 + nt * 8 + 2 * (lane & 3);
            atomicAdd(&d_WtW[r * HID + c],           acc[mt][nt][0]);
            atomicAdd(&d_WtW[r * HID + c + 1],       acc[mt][nt][1]);
            atomicAdd(&d_WtW[(r + 8) * HID + c],     acc[mt][nt][2]);
            atomicAdd(&d_WtW[(r + 8) * HID + c + 1], acc[mt][nt][3]);
        }
}

// ---------------- logits scan + multinomial logprob ----------------
__global__ __launch_bounds__(512) void k_mult(const float* __restrict__ x) {
    int b = blockIdx.x, t = threadIdx.x, lane = t & 31, wid = t >> 5;
    const float* xb = x + (size_t)b * DD;
    const float* db = d_dlt + (size_t)b * (DD + 1);
    __shared__ float wtot[16], woff[16];
    __shared__ float redf[16];
    float carry = 0.f, sexp = 0.f, sxl = 0.f;

    for (int base = 0; base < DD; base += 4096) {
        float loc[8], xv[8]; float run = 0.f;
        int i0 = base + t * 8;
        #pragma unroll
        for (int v = 0; v < 8; v++) {
            int i = i0 + v;
            float dv = (i < DD) ? db[i] : 0.f;
            xv[v] = (i < DD) ? xb[i] : 0.f;
            run += dv;
            loc[v] = run;
        }
        float v = run;
        #pragma unroll
        for (int off = 1; off < 32; off <<= 1) {
            float nv = __shfl_up_sync(0xffffffffu, v, off);
            if (lane >= off) v += nv;
        }
        if (lane == 31) wtot[wid] = v;
        __syncthreads();
        if (wid == 0) {
            float w = (lane < 16) ? wtot[lane] : 0.f;
            #pragma unroll
            for (int off = 1; off < 16; off <<= 1) {
                float nv = __shfl_up_sync(0xffffffffu, w, off);
                if (lane >= off) w += nv;
            }
            if (lane < 16) woff[lane] = w;
        }
        __syncthreads();
        float basf = carry + (wid > 0 ? woff[wid - 1] : 0.f) + (v - run);
        #pragma unroll
        for (int u = 0; u < 8; u++) {
            int i = i0 + u;
            if (i < DD) {
                float logit = basf + loc[u];
                sexp += expf(logit);
                sxl = fmaf(xv[u], logit, sxl);
            }
        }
        carry += woff[15];
        __syncthreads();
    }
    #pragma unroll
    for (int off = 16; off; off >>= 1) sexp += __shfl_down_sync(0xffffffffu, sexp, off);
    if (lane == 0) redf[wid] = sexp;
    __syncthreads();
    double tsexp = 0.0;
    if (t == 0) { for (int i = 0; i < 16; i++) tsexp += (double)redf[i]; }
    __syncthreads();
    #pragma unroll
    for (int off = 16; off; off >>= 1) sxl += __shfl_down_sync(0xffffffffu, sxl, off);
    if (lane == 0) redf[wid] = sxl;
    __syncthreads();
    if (t == 0) {
        double s = 0.0; for (int i = 0; i < 16; i++) s += (double)redf[i];
        double sx = d_sumx[b];
        d_mult[b] = lgamma(sx + 1.0) - d_sumlg[b] + s - sx * log(tsexp);
    }
}

// ---------------- u = (g - z@WtW)*sD, quad pieces ----------------
__global__ void k_uquad(const float* __restrict__ vlv) {
    int b = blockIdx.x, k = threadIdx.x;
    __shared__ float zs[128];
    __shared__ float rd[128];
    zs[k] = d_z[b * HID + k];
    __syncthreads();
    float wv = 0.f;
    #pragma unroll 8
    for (int k2 = 0; k2 < 128; k2++) wv = fmaf(zs[k2], d_WtW[k2 * HID + k], wv);
    float g = d_g[b * HID + k];
    float sd = expf(0.5f * vlv[k]);
    d_u[b * HID + k] = (g - wv) * sd;
    float z = zs[k];

    rd[k] = z * g; __syncthreads();
    for (int off = 64; off; off >>= 1) { if (k < off) rd[k] += rd[k + off]; __syncthreads(); }
    if (k == 0) d_zg[b] = rd[0];
    __syncthreads();
    rd[k] = z * wv; __syncthreads();
    for (int off = 64; off; off >>= 1) { if (k < off) rd[k] += rd[k + off]; __syncthreads(); }
    if (k == 0) d_zWz[b] = rd[0];
    __syncthreads();
    rd[k] = z * z; __syncthreads();
    for (int off = 64; off; off >>= 1) { if (k < off) rd[k] += rd[k + off]; __syncthreads(); }
    if (k == 0) d_z2[b] = rd[0];
}

// ---------------- final: panel Cholesky + solve + loss ----------------
__global__ __launch_bounds__(512) void k_final(const float* __restrict__ vlv,
                                               const float* __restrict__ lss_ptr,
                                               float* __restrict__ out) {
    extern __shared__ float smf[];
    float* Mm = smf;
    float* R  = smf + 128 * 129;
    __shared__ __align__(16) float Lp[120 * 8];
    __shared__ float sinv[8];
    __shared__ float sD[128];
    __shared__ double s_ld;
    __shared__ double red[512];
    int t = threadIdx.x, lane = t & 31;
    float lss = *lss_ptr;
    float var = expf(lss);
    float ivar = 1.f / var;
    if (t < 128) sD[t] = expf(0.5f * vlv[t]);
    __syncthreads();
    for (int idx = t; idx < 128 * 128; idx += 512) {
        int i = idx >> 7, j = idx & 127;
        float m = sD[i] * d_WtW[idx] * sD[j] * ivar;
        if (i == j) m += 1.f;
        Mm[i * 129 + j] = m;
    }
    for (int idx = t; idx < 128 * 128; idx += 512) {
        int b = idx >> 7, i = idx & 127;
        R[i * 129 + b] = d_u[idx];
    }
    __syncthreads();

    float qacc = 0.f;
    double ldacc = 0.0;

    for (int p = 0; p < 16; p++) {
        int k0 = 8 * p;
        if (t < 32) {
            int r = lane & 7;
            float v[8];
            #pragma unroll
            for (int c = 0; c < 8; c++) v[c] = Mm[(k0 + r) * 129 + k0 + c];
            #pragma unroll
            for (int kk = 0; kk < 8; kk++) {
                float dkk = __shfl_sync(0xffffffffu, v[kk], kk);
                float d = sqrtf(dkk);
                float inv = 1.f / d;
                if (lane == kk) { v[kk] = d; ldacc += 2.0 * log((double)d); }
                if (r > kk && lane != kk) v[kk] *= inv;
                #pragma unroll
                for (int c = kk + 1; c < 8; c++) {
                    float Lck = __shfl_sync(0xffffffffu, v[kk], c);
                    if (r > kk) v[c] -= v[kk] * Lck;
                }
            }
            if (lane < 8) {
                #pragma unroll
                for (int c = 0; c < 8; c++) Mm[(k0 + r) * 129 + k0 + c] = v[c];
                sinv[r] = 1.f / v[r];
            }
        }
        __syncthreads();

        int nrem = 120 - k0;
        if (t < nrem) {
            int i = k0 + 8 + t;
            float a[8];
            #pragma unroll
            for (int c = 0; c < 8; c++) a[c] = Mm[i * 129 + k0 + c];
            #pragma unroll
            for (int c = 0; c < 8; c++) {
                float s = a[c];
                #pragma unroll
                for (int q = 0; q < 8; q++) if (q < c) s -= a[q] * Mm[(k0 + c) * 129 + k0 + q];
                a[c] = s * sinv[c];
            }
            #pragma unroll
            for (int c = 0; c < 8; c++) { Mm[i * 129 + k0 + c] = a[c]; Lp[t * 8 + c] = a[c]; }
        } else if (t >= 256 && t < 384) {
            int b = t - 256;
            float y[8];
            #pragma unroll
            for (int c = 0; c < 8; c++) y[c] = R[(k0 + c) * 129 + b];
            #pragma unroll
            for (int c = 0; c < 8; c++) {
                float s = y[c];
                #pragma unroll
                for (int q = 0; q < 8; q++) if (q < c) s -= y[q] * Mm[(k0 + c) * 129 + k0 + q];
                y[c] = s * sinv[c];
                qacc = fmaf(y[c], y[c], qacc);
            }
            #pragma unroll
            for (int c = 0; c < 8; c++) R[(k0 + c) * 129 + b] = y[c];
        }
        __syncthreads();

        int base = k0 + 8, n = 128 - base;
        if (n > 0) {
            int io = t & 127, jg = t >> 7;
            if (io < n) {
                int i = base + io;
                float Li[8];
                #pragma unroll
                for (int q = 0; q < 8; q++) Li[q] = Lp[io * 8 + q];
                for (int jo = jg; jo < n; jo += 4) {
                    int j = base + jo;
                    const float4* lp4 = (const float4*)&Lp[jo * 8];
                    float4 L0 = lp4[0], L1 = lp4[1];
                    float s = Mm[i * 129 + j];
                    s -= Li[0] * L0.x + Li[1] * L0.y + Li[2] * L0.z + Li[3] * L0.w
                       + Li[4] * L1.x + Li[5] * L1.y + Li[6] * L1.z + Li[7] * L1.w;
                    Mm[i * 129 + j] = s;
                }
            }
            {
                int b = t & 127, ig = t >> 7;
                float y[8];
                #pragma unroll
                for (int q = 0; q < 8; q++) y[q] = R[(k0 + q) * 129 + b];
                for (int io2 = ig; io2 < n; io2 += 4) {
                    int i = base + io2;
                    const float4* lp4 = (const float4*)&Lp[io2 * 8];
                    float4 L0 = lp4[0], L1 = lp4[1];
                    float s = R[i * 129 + b];
                    s -= y[0] * L0.x + y[1] * L0.y + y[2] * L0.z + y[3] * L0.w
                       + y[4] * L1.x + y[5] * L1.y + y[6] * L1.z + y[7] * L1.w;
                    R[i * 129 + b] = s;
                }
            }
        }
        __syncthreads();
    }

    if (t < 32) {
        #pragma unroll
        for (int off = 16; off; off >>= 1) ldacc += __shfl_down_sync(0xffffffffu, ldacc, off);
        if (lane == 0) s_ld = ldacc;
    }
    __syncthreads();

    double acc = 0.0;
    if (t >= 256 && t < 384) {
        int b = t - 256;
        float quad = (d_eta2[b] - 2.f * d_zg[b] + d_zWz[b]) * ivar - qacc * ivar * ivar;
        double logdet = (double)DM1 * (double)lss + s_ld;
        double ll = -0.5 * ((double)DM1 * LOG2PI + logdet + (double)quad);
        acc = ll + d_mult[b] - 0.5 * (double)d_z2[b] / 128.0;
    }
    red[t] = acc;
    __syncthreads();
    for (int off = 256; off; off >>= 1) { if (t < off) red[t] += red[t + off]; __syncthreads(); }
    if (t == 0) {
        double total = red[0] / 128.0 - 0.5 * LOG2PI;
        out[0] = (float)(-total);
    }
}

// ---------------- launcher (multi-stream DAG under graph capture) ----------------
static cudaStream_t s1, s2, s3;
static cudaEvent_t ev_root, ev_meta, ev_ms, ev_scan, ev_enc, ev_dect, ev_g, ev_w, ev_mult;
static bool g_init = false;

extern "C" void kernel_launch(void* const* d_in, const int* in_sizes, int n_in,
                              void* d_out, int out_size) {
    const float* x     = (const float*)d_in[0];
    const int*   rows  = (const int*)  d_in[1];
    const int*   cols  = (const int*)  d_in[2];
    const float* vals  = (const float*)d_in[3];
    const float* enc_w = (const float*)d_in[4];
    const float* dec_w = (const float*)d_in[5];
    const float* vlv   = (const float*)d_in[6];
    const float* lss   = (const float*)d_in[7];
    const float* eta   = (const float*)d_in[8];
    int nnz = in_sizes[1];
    float* out = (float*)d_out;

    if (!g_init) {
        cudaStreamCreateWithFlags(&s1, cudaStreamNonBlocking);
        cudaStreamCreateWithFlags(&s2, cudaStreamNonBlocking);
        cudaStreamCreateWithFlags(&s3, cudaStreamNonBlocking);
        cudaEventCreateWithFlags(&ev_root, cudaEventDisableTiming);
        cudaEventCreateWithFlags(&ev_meta, cudaEventDisableTiming);
        cudaEventCreateWithFlags(&ev_ms,   cudaEventDisableTiming);
        cudaEventCreateWithFlags(&ev_scan, cudaEventDisableTiming);
        cudaEventCreateWithFlags(&ev_enc,  cudaEventDisableTiming);
        cudaEventCreateWithFlags(&ev_dect, cudaEventDisableTiming);
        cudaEventCreateWithFlags(&ev_g,    cudaEventDisableTiming);
        cudaEventCreateWithFlags(&ev_w,    cudaEventDisableTiming);
        cudaEventCreateWithFlags(&ev_mult, cudaEventDisableTiming);
        cudaFuncSetAttribute(k_final, cudaFuncAttributeMaxDynamicSharedMemorySize,
                             2 * 128 * 129 * (int)sizeof(float));
        g_init = true;
    }

    void *p_dlt, *p_z, *p_g, *p_w, *p_e2;
    cudaGetSymbolAddress(&p_dlt, d_dlt);
    cudaGetSymbolAddress(&p_z,   d_z);
    cudaGetSymbolAddress(&p_g,   d_g);
    cudaGetSymbolAddress(&p_w,   d_WtW);
    cudaGetSymbolAddress(&p_e2,  d_eta2);

    // fork
    cudaEventRecord(ev_root, 0);
    cudaStreamWaitEvent(s1, ev_root, 0);
    cudaStreamWaitEvent(s2, ev_root, 0);
    cudaStreamWaitEvent(s3, ev_root, 0);

    // s0: meta chain
    cudaMemsetAsync(p_z, 0, BB * HID * sizeof(float), 0);
    k_meta<<<(DM1 + 255) / 256, 256, 0, 0>>>(rows, cols, vals, nnz);
    cudaEventRecord(ev_meta, 0);

    // s1: scan
    k_scan_lx<<<BB, 512, 0, s1>>>(x);
    cudaEventRecord(ev_scan, s1);

    // s2: memsets -> cvt_eta (needs meta) -> gemm_g (needs dect) -> mult (needs scan)
    cudaMemsetAsync(p_dlt, 0, (size_t)BB * (DD + 1) * sizeof(float), s2);
    cudaMemsetAsync(p_g,   0, BB * HID * sizeof(float), s2);
    cudaMemsetAsync(p_w,   0, HID * HID * sizeof(float), s2);
    cudaMemsetAsync(p_e2,  0, BB * sizeof(float), s2);
    cudaEventRecord(ev_ms, s2);
    cudaStreamWaitEvent(s2, ev_meta, 0);
    {
        dim3 gcv((ST + 511) / 512, BB);
        k_cvt_eta<<<gcv, 256, 0, s2>>>(eta);
    }

    // s3: cvt_enc -> trans_dec -> gemm_w (needs memset w)
    {
        dim3 gcv((ST + 511) / 512, HID);
        k_cvt_enc<<<gcv, 256, 0, s3>>>(enc_w);
    }
    cudaEventRecord(ev_enc, s3);
    k_trans_dec<<<ST / 64, 256, 0, s3>>>(dec_w);
    cudaEventRecord(ev_dect, s3);
    cudaStreamWaitEvent(s3, ev_ms, 0);
    k_gemm_w<<<NBLK2, 256, 0, s3>>>();
    cudaEventRecord(ev_w, s3);

    // s2 cont: gemm_g then mult
    cudaStreamWaitEvent(s2, ev_dect, 0);
    k_gemm_g<<<NBLK2, 256, 0, s2>>>();
    cudaEventRecord(ev_g, s2);
    cudaStreamWaitEvent(s2, ev_scan, 0);
    k_mult<<<BB, 512, 0, s2>>>(x);
    cudaEventRecord(ev_mult, s2);

    // s0 cont: hxb -> gemm_z -> uquad -> final
    cudaStreamWaitEvent(0, ev_scan, 0);
    {
        dim3 ghx(ST / 256, BB);
        k_hxb<<<ghx, 256, 0, 0>>>();
    }
    cudaStreamWaitEvent(0, ev_enc, 0);
    k_gemm_z<<<NBLK2, 256, 0, 0>>>();
    cudaStreamWaitEvent(0, ev_g, 0);
    cudaStreamWaitEvent(0, ev_w, 0);
    k_uquad<<<BB, 128, 0, 0>>>(vlv);
    cudaStreamWaitEvent(0, ev_mult, 0);
    k_final<<<1, 512, 2 * 128 * 129 * sizeof(float), 0>>>(vlv, lss, out);
}